// round 1
// baseline (speedup 1.0000x reference)
#include <cuda_runtime.h>

// deeds_graph: N=10000 volumes of 13^3, K=8 neighbors.
// Pipeline: S1 = smooth(a1 + a0*cost)
//           c2 = a4 + a2*(a1+a0*cost) + a3 * (sum_k w*S1[knn]) / norm
//           S2 = smooth(c2)
//           out = a5 * (sum_k w*S2[knn]) / norm
// smooth = edge-pad(3) -> maxpool3 -> avgpool3 -> avgpool3
//        = separable: 1D max3 per dim (19->17), 1D 5-tap [1,2,3,2,1]/9 per dim (17->13)

#define NVOX 2197          // 13^3
#define NMAX 10000
#define KNN  8
#define XCH_SIZE (19*17*17)

__device__ float g_S1[(size_t)NMAX * NVOX];
__device__ float g_S2[(size_t)NMAX * NVOX];

__device__ __forceinline__ float max3f(float a, float b, float c) {
    return fmaxf(fmaxf(a, b), c);
}

// Thread layout: blockDim = (32, 19). lx = padded-x lane (valid 0..18),
// ly = padded-y. Each thread holds the 19 padded-z values of its (x,y)
// column in registers. z passes: registers. x passes: warp shuffles.
// y passes: smem exchange. Result written to outb[z*169 + y*13 + x].
__device__ __forceinline__ void smooth_core(float col[19], float* xch, float* outb,
                                            int lx, int ly) {
    const unsigned FULL = 0xFFFFFFFFu;

    // ---- max over z: 19 -> 17 (registers) ----
    float a[17];
    #pragma unroll
    for (int z = 0; z < 17; z++) a[z] = max3f(col[z], col[z+1], col[z+2]);

    // ---- max over x: shuffle (output valid for lx < 17) ----
    #pragma unroll
    for (int z = 0; z < 17; z++) {
        float n1 = __shfl_down_sync(FULL, a[z], 1);
        float n2 = __shfl_down_sync(FULL, a[z], 2);
        a[z] = max3f(a[z], n1, n2);
    }

    // ---- max over y: smem exchange. xch layout [y(19)][z(17)][x(17)] ----
    if (lx < 17) {
        #pragma unroll
        for (int z = 0; z < 17; z++) xch[(ly*17 + z)*17 + lx] = a[z];
    }
    __syncthreads();
    float b[17];
    if (lx < 17 && ly < 17) {
        #pragma unroll
        for (int z = 0; z < 17; z++) {
            float n1 = xch[((ly+1)*17 + z)*17 + lx];
            float n2 = xch[((ly+2)*17 + z)*17 + lx];
            b[z] = max3f(a[z], n1, n2);
        }
    } else {
        #pragma unroll
        for (int z = 0; z < 17; z++) b[z] = 0.0f;   // never consumed
    }

    // ---- 5-tap [1,2,3,2,1] over z: 17 -> 13 (registers) ----
    float c[13];
    #pragma unroll
    for (int z = 0; z < 13; z++)
        c[z] = b[z] + 2.0f*b[z+1] + 3.0f*b[z+2] + 2.0f*b[z+3] + b[z+4];

    // ---- 5-tap over x: shuffle (output valid for lx < 13) ----
    #pragma unroll
    for (int z = 0; z < 13; z++) {
        float s1 = __shfl_down_sync(FULL, c[z], 1);
        float s2 = __shfl_down_sync(FULL, c[z], 2);
        float s3 = __shfl_down_sync(FULL, c[z], 3);
        float s4 = __shfl_down_sync(FULL, c[z], 4);
        c[z] = c[z] + 2.0f*s1 + 3.0f*s2 + 2.0f*s3 + s4;
    }

    // ---- 5-tap over y: smem exchange (reuse xch). layout [y(17)][z(13)][x(13)] ----
    __syncthreads();   // protect xch reuse
    if (lx < 13 && ly < 17) {
        #pragma unroll
        for (int z = 0; z < 13; z++) xch[(ly*13 + z)*13 + lx] = c[z];
    }
    __syncthreads();
    if (lx < 13 && ly < 13) {
        #pragma unroll
        for (int z = 0; z < 13; z++) {
            float v = c[z]
                    + 2.0f*xch[((ly+1)*13 + z)*13 + lx]
                    + 3.0f*xch[((ly+2)*13 + z)*13 + lx]
                    + 2.0f*xch[((ly+3)*13 + z)*13 + lx]
                    +      xch[((ly+4)*13 + z)*13 + lx];
            outb[z*169 + ly*13 + lx] = v * (1.0f/729.0f);
        }
    }
}

// ---------------- Kernel A: S1 = smooth(a1 + a0*cost) ----------------
__global__ void __launch_bounds__(608) k_smooth1(
    const float* __restrict__ cost, const float* __restrict__ alpha) {
    __shared__ float xch[XCH_SIZE];
    __shared__ float outb[NVOX];
    int n = blockIdx.x;
    int lx = threadIdx.x, ly = threadIdx.y;
    float a0 = alpha[0], a1 = alpha[1];
    const float* src = cost + (size_t)n * NVOX;

    int cx = min(max(lx - 3, 0), 12);
    int cy = min(max(ly - 3, 0), 12);
    float col[19];
    #pragma unroll
    for (int z = 0; z < 19; z++) {
        int cz = min(max(z - 3, 0), 12);
        col[z] = a1 + a0 * __ldg(&src[cz*169 + cy*13 + cx]);
    }
    smooth_core(col, xch, outb, lx, ly);
    __syncthreads();
    float* dst = g_S1 + (size_t)n * NVOX;
    for (int i = ly*32 + lx; i < NVOX; i += 608) dst[i] = outb[i];
}

// ------- Kernel B: c2 = blend(cost, gather(S1)); S2 = smooth(c2) -------
__global__ void __launch_bounds__(608) k_gather_smooth(
    const float* __restrict__ cost, const int* __restrict__ knn,
    const float* __restrict__ dist, const float* __restrict__ alpha) {
    __shared__ float xch[XCH_SIZE];
    __shared__ float outb[NVOX];
    __shared__ float c2[NVOX];
    __shared__ float wsh[KNN];
    __shared__ int   nbsh[KNN];
    __shared__ float sninv;
    int n = blockIdx.x;
    int lx = threadIdx.x, ly = threadIdx.y;
    int tid = ly*32 + lx;

    if (tid == 0) {
        float s = 0.0f;
        #pragma unroll
        for (int k = 0; k < KNN; k++) {
            float w = expf(-dist[n*KNN + k] * (1.0f/200.0f));  // 2*SIGMA^2 = 200
            wsh[k] = w; s += w;
            nbsh[k] = knn[n*KNN + k];
        }
        sninv = 1.0f / s;
    }
    __syncthreads();

    float a0 = alpha[0], a1 = alpha[1], a2 = alpha[2], a3 = alpha[3], a4 = alpha[4];
    float wk[KNN]; long nb[KNN];
    #pragma unroll
    for (int k = 0; k < KNN; k++) { wk[k] = wsh[k]; nb[k] = (long)nbsh[k] * NVOX; }
    float ninv = sninv;

    const float* src = cost + (size_t)n * NVOX;
    for (int v = tid; v < NVOX; v += 608) {
        float acc = 0.0f;
        #pragma unroll
        for (int k = 0; k < KNN; k++) acc += wk[k] * __ldg(&g_S1[nb[k] + v]);
        float c1 = a1 + a0 * __ldg(&src[v]);
        c2[v] = a4 + a2*c1 + a3*(acc*ninv);
    }
    __syncthreads();

    int cx = min(max(lx - 3, 0), 12);
    int cy = min(max(ly - 3, 0), 12);
    float col[19];
    #pragma unroll
    for (int z = 0; z < 19; z++) {
        int cz = min(max(z - 3, 0), 12);
        col[z] = c2[cz*169 + cy*13 + cx];
    }
    smooth_core(col, xch, outb, lx, ly);
    __syncthreads();
    float* dst = g_S2 + (size_t)n * NVOX;
    for (int i = tid; i < NVOX; i += 608) dst[i] = outb[i];
}

// ---------------- Kernel C: out = a5 * gather(S2) / norm ----------------
__global__ void __launch_bounds__(256) k_gather_out(
    const int* __restrict__ knn, const float* __restrict__ dist,
    const float* __restrict__ alpha, float* __restrict__ out) {
    __shared__ float wsh[KNN];
    __shared__ int   nbsh[KNN];
    __shared__ float sscale;
    int n = blockIdx.x;
    int tid = threadIdx.x;
    if (tid == 0) {
        float s = 0.0f;
        #pragma unroll
        for (int k = 0; k < KNN; k++) {
            float w = expf(-dist[n*KNN + k] * (1.0f/200.0f));
            wsh[k] = w; s += w;
            nbsh[k] = knn[n*KNN + k];
        }
        sscale = alpha[5] / s;
    }
    __syncthreads();
    float wk[KNN]; long nb[KNN];
    #pragma unroll
    for (int k = 0; k < KNN; k++) { wk[k] = wsh[k]; nb[k] = (long)nbsh[k] * NVOX; }
    float sc = sscale;
    float* dst = out + (size_t)n * NVOX;
    for (int v = tid; v < NVOX; v += 256) {
        float acc = 0.0f;
        #pragma unroll
        for (int k = 0; k < KNN; k++) acc += wk[k] * __ldg(&g_S2[nb[k] + v]);
        dst[v] = acc * sc;
    }
}

extern "C" void kernel_launch(void* const* d_in, const int* in_sizes, int n_in,
                              void* d_out, int out_size) {
    const float* cost  = (const float*)d_in[0];
    const int*   knn   = (const int*)d_in[1];
    const float* dist  = (const float*)d_in[2];
    const float* alpha = (const float*)d_in[3];
    float* out = (float*)d_out;
    int N = in_sizes[0] / NVOX;   // 10000

    dim3 blk(32, 19);
    k_smooth1<<<N, blk>>>(cost, alpha);
    k_gather_smooth<<<N, blk>>>(cost, knn, dist, alpha);
    k_gather_out<<<N, 256>>>(knn, dist, alpha, out);
}

// round 3
// speedup vs baseline: 1.5866x; 1.5866x over previous
#include <cuda_runtime.h>
#include <cuda_fp16.h>

// deeds_graph: N=10000 volumes of 13^3, K=8 neighbors.
// S1 = smooth(a1 + a0*cost)                          [fp16 scratch, padded]
// c2 = a4 + a2*(a1+a0*cost) + a3 * gatherW(S1)/norm
// S2 = smooth(c2)                                    [fp16 scratch, padded]
// out = a5 * gatherW(S2) / norm
// smooth = edge-pad(3) -> max3 -> avg3 -> avg3 (separable: max3 per dim, 5-tap [1,2,3,2,1]/9 per dim)

#define NVOX 2197          // 13^3
#define VPAD 2208          // padded halves per volume (16B-aligned chunks)
#define NCHUNK 276         // VPAD / 8 halves per uint4
#define NMAX 10000
#define KNN  8
#define XCH_SIZE (19*17*17)

__device__ __half g_S1[(size_t)NMAX * VPAD];
__device__ __half g_S2[(size_t)NMAX * VPAD];

__device__ __forceinline__ float max3f(float a, float b, float c) {
    return fmaxf(fmaxf(a, b), c);
}

// blockDim = (32,19). lx = padded-x lane (valid 0..18), ly = padded-y.
// Each thread holds the 19 padded-z values of its (x,y) column in registers.
// z passes: registers. x passes: warp shuffles. y passes: smem exchange.
// Result -> outb[z*169 + y*13 + x] (fp32).
__device__ __forceinline__ void smooth_core(float col[19], float* xch, float* outb,
                                            int lx, int ly) {
    const unsigned FULL = 0xFFFFFFFFu;

    float a[17];
    #pragma unroll
    for (int z = 0; z < 17; z++) a[z] = max3f(col[z], col[z+1], col[z+2]);

    #pragma unroll
    for (int z = 0; z < 17; z++) {
        float n1 = __shfl_down_sync(FULL, a[z], 1);
        float n2 = __shfl_down_sync(FULL, a[z], 2);
        a[z] = max3f(a[z], n1, n2);
    }

    if (lx < 17) {
        #pragma unroll
        for (int z = 0; z < 17; z++) xch[(ly*17 + z)*17 + lx] = a[z];
    }
    __syncthreads();
    float b[17];
    if (lx < 17 && ly < 17) {
        #pragma unroll
        for (int z = 0; z < 17; z++) {
            float n1 = xch[((ly+1)*17 + z)*17 + lx];
            float n2 = xch[((ly+2)*17 + z)*17 + lx];
            b[z] = max3f(a[z], n1, n2);
        }
    } else {
        #pragma unroll
        for (int z = 0; z < 17; z++) b[z] = 0.0f;
    }

    float c[13];
    #pragma unroll
    for (int z = 0; z < 13; z++)
        c[z] = b[z] + 2.0f*b[z+1] + 3.0f*b[z+2] + 2.0f*b[z+3] + b[z+4];

    #pragma unroll
    for (int z = 0; z < 13; z++) {
        float s1 = __shfl_down_sync(FULL, c[z], 1);
        float s2 = __shfl_down_sync(FULL, c[z], 2);
        float s3 = __shfl_down_sync(FULL, c[z], 3);
        float s4 = __shfl_down_sync(FULL, c[z], 4);
        c[z] = c[z] + 2.0f*s1 + 3.0f*s2 + 2.0f*s3 + s4;
    }

    __syncthreads();
    if (lx < 13 && ly < 17) {
        #pragma unroll
        for (int z = 0; z < 13; z++) xch[(ly*13 + z)*13 + lx] = c[z];
    }
    __syncthreads();
    if (lx < 13 && ly < 13) {
        #pragma unroll
        for (int z = 0; z < 13; z++) {
            float v = c[z]
                    + 2.0f*xch[((ly+1)*13 + z)*13 + lx]
                    + 3.0f*xch[((ly+2)*13 + z)*13 + lx]
                    + 2.0f*xch[((ly+3)*13 + z)*13 + lx]
                    +      xch[((ly+4)*13 + z)*13 + lx];
            outb[z*169 + ly*13 + lx] = v * (1.0f/729.0f);
        }
    }
}

// copy fp32 outb[0..2196] -> half dst[0..2207] (pad = 0), half2 stores
__device__ __forceinline__ void store_half_padded(const float* outb, __half* dst, int tid) {
    for (int i = tid; i < VPAD/2; i += 608) {
        int i0 = 2*i, i1 = 2*i + 1;
        float f0 = (i0 < NVOX) ? outb[i0] : 0.0f;
        float f1 = (i1 < NVOX) ? outb[i1] : 0.0f;
        *reinterpret_cast<__half2*>(dst + i0) = __floats2half2_rn(f0, f1);
    }
}

// ---------------- Kernel A: S1 = smooth(a1 + a0*cost) ----------------
__global__ void __launch_bounds__(608) k_smooth1(
    const float* __restrict__ cost, const float* __restrict__ alpha) {
    __shared__ float xch[XCH_SIZE];
    __shared__ float outb[NVOX];
    int n = blockIdx.x;
    int lx = threadIdx.x, ly = threadIdx.y;
    float a0 = alpha[0], a1 = alpha[1];
    const float* src = cost + (size_t)n * NVOX;

    int cx = min(max(lx - 3, 0), 12);
    int cy = min(max(ly - 3, 0), 12);
    float col[19];
    #pragma unroll
    for (int z = 0; z < 19; z++) {
        int cz = min(max(z - 3, 0), 12);
        col[z] = a1 + a0 * __ldg(&src[cz*169 + cy*13 + cx]);
    }
    smooth_core(col, xch, outb, lx, ly);
    __syncthreads();
    store_half_padded(outb, g_S1 + (size_t)n * VPAD, ly*32 + lx);
}

// ------- Kernel B: c2 = blend(cost, gatherW(S1)); S2 = smooth(c2) -------
__global__ void __launch_bounds__(608) k_gather_smooth(
    const float* __restrict__ cost, const int* __restrict__ knn,
    const float* __restrict__ dist, const float* __restrict__ alpha) {
    __shared__ float xch[XCH_SIZE];
    __shared__ float outb[NVOX];
    __shared__ float c2[NVOX];
    __shared__ float wsh[KNN];
    __shared__ int   nbsh[KNN];
    __shared__ float sninv;
    int n = blockIdx.x;
    int lx = threadIdx.x, ly = threadIdx.y;
    int tid = ly*32 + lx;

    if (tid == 0) {
        float s = 0.0f;
        #pragma unroll
        for (int k = 0; k < KNN; k++) {
            float w = expf(-dist[n*KNN + k] * (1.0f/200.0f));  // 2*SIGMA^2 = 200
            wsh[k] = w; s += w;
            nbsh[k] = knn[n*KNN + k];
        }
        sninv = 1.0f / s;
    }
    __syncthreads();

    float a0 = alpha[0], a1 = alpha[1], a2 = alpha[2], a3 = alpha[3], a4 = alpha[4];
    float wk[KNN]; const uint4* nbp[KNN];
    #pragma unroll
    for (int k = 0; k < KNN; k++) {
        wk[k] = wsh[k];
        nbp[k] = reinterpret_cast<const uint4*>(g_S1 + (size_t)nbsh[k] * VPAD);
    }
    float ninv = sninv;

    const float* src = cost + (size_t)n * NVOX;
    for (int cch = tid; cch < NCHUNK; cch += 608) {
        float acc[8];
        #pragma unroll
        for (int j = 0; j < 8; j++) acc[j] = 0.0f;
        #pragma unroll
        for (int k = 0; k < KNN; k++) {
            uint4 raw = __ldg(&nbp[k][cch]);
            __half2 h0 = *reinterpret_cast<__half2*>(&raw.x);
            __half2 h1 = *reinterpret_cast<__half2*>(&raw.y);
            __half2 h2 = *reinterpret_cast<__half2*>(&raw.z);
            __half2 h3 = *reinterpret_cast<__half2*>(&raw.w);
            float2 f0 = __half22float2(h0), f1 = __half22float2(h1);
            float2 f2 = __half22float2(h2), f3 = __half22float2(h3);
            acc[0] += wk[k]*f0.x; acc[1] += wk[k]*f0.y;
            acc[2] += wk[k]*f1.x; acc[3] += wk[k]*f1.y;
            acc[4] += wk[k]*f2.x; acc[5] += wk[k]*f2.y;
            acc[6] += wk[k]*f3.x; acc[7] += wk[k]*f3.y;
        }
        int vbase = cch * 8;
        #pragma unroll
        for (int j = 0; j < 8; j++) {
            int v = vbase + j;
            if (v < NVOX) {
                float c1 = a1 + a0 * __ldg(&src[v]);
                c2[v] = a4 + a2*c1 + a3*(acc[j]*ninv);
            }
        }
    }
    __syncthreads();

    int cx = min(max(lx - 3, 0), 12);
    int cy = min(max(ly - 3, 0), 12);
    float col[19];
    #pragma unroll
    for (int z = 0; z < 19; z++) {
        int cz = min(max(z - 3, 0), 12);
        col[z] = c2[cz*169 + cy*13 + cx];
    }
    smooth_core(col, xch, outb, lx, ly);
    __syncthreads();
    store_half_padded(outb, g_S2 + (size_t)n * VPAD, tid);
}

// ---------------- Kernel C: out = a5 * gatherW(S2) / norm ----------------
__global__ void __launch_bounds__(256) k_gather_out(
    const int* __restrict__ knn, const float* __restrict__ dist,
    const float* __restrict__ alpha, float* __restrict__ out) {
    __shared__ float wsh[KNN];
    __shared__ int   nbsh[KNN];
    __shared__ float sscale;
    int n = blockIdx.x;
    int tid = threadIdx.x;
    if (tid == 0) {
        float s = 0.0f;
        #pragma unroll
        for (int k = 0; k < KNN; k++) {
            float w = expf(-dist[n*KNN + k] * (1.0f/200.0f));
            wsh[k] = w; s += w;
            nbsh[k] = knn[n*KNN + k];
        }
        sscale = alpha[5] / s;
    }
    __syncthreads();
    float wk[KNN]; const uint4* nbp[KNN];
    #pragma unroll
    for (int k = 0; k < KNN; k++) {
        wk[k] = wsh[k];
        nbp[k] = reinterpret_cast<const uint4*>(g_S2 + (size_t)nbsh[k] * VPAD);
    }
    float sc = sscale;
    float* dst = out + (size_t)n * NVOX;
    for (int cch = tid; cch < NCHUNK; cch += 256) {
        float acc[8];
        #pragma unroll
        for (int j = 0; j < 8; j++) acc[j] = 0.0f;
        #pragma unroll
        for (int k = 0; k < KNN; k++) {
            uint4 raw = __ldg(&nbp[k][cch]);
            __half2 h0 = *reinterpret_cast<__half2*>(&raw.x);
            __half2 h1 = *reinterpret_cast<__half2*>(&raw.y);
            __half2 h2 = *reinterpret_cast<__half2*>(&raw.z);
            __half2 h3 = *reinterpret_cast<__half2*>(&raw.w);
            float2 f0 = __half22float2(h0), f1 = __half22float2(h1);
            float2 f2 = __half22float2(h2), f3 = __half22float2(h3);
            acc[0] += wk[k]*f0.x; acc[1] += wk[k]*f0.y;
            acc[2] += wk[k]*f1.x; acc[3] += wk[k]*f1.y;
            acc[4] += wk[k]*f2.x; acc[5] += wk[k]*f2.y;
            acc[6] += wk[k]*f3.x; acc[7] += wk[k]*f3.y;
        }
        int vbase = cch * 8;
        #pragma unroll
        for (int j = 0; j < 8; j++) {
            int v = vbase + j;
            if (v < NVOX) dst[v] = acc[j] * sc;
        }
    }
}

extern "C" void kernel_launch(void* const* d_in, const int* in_sizes, int n_in,
                              void* d_out, int out_size) {
    const float* cost  = (const float*)d_in[0];
    const int*   knn   = (const int*)d_in[1];
    const float* dist  = (const float*)d_in[2];
    const float* alpha = (const float*)d_in[3];
    float* out = (float*)d_out;
    int N = in_sizes[0] / NVOX;   // 10000

    dim3 blk(32, 19);
    k_smooth1<<<N, blk>>>(cost, alpha);
    k_gather_smooth<<<N, blk>>>(cost, knn, dist, alpha);
    k_gather_out<<<N, 256>>>(knn, dist, alpha, out);
}

// round 5
// speedup vs baseline: 1.9263x; 1.2141x over previous
#include <cuda_runtime.h>
#include <cuda_fp16.h>

// deeds_graph: N=10000 volumes of 13^3, K=8 neighbors.
// Volume-PAIRED half2 pipeline: block handles volumes (2p, 2p+1) packed in half2 lanes.
// S1 = smooth(a1 + a0*cost)   [half scratch]
// c2 = a4 + a2*(a1+a0*cost) + a3 * gatherW(S1)/norm ; S2 = smooth(c2)
// out = a5 * gatherW(S2) / norm
// smooth = edge-pad(3) -> max3^3 -> (5-tap [1,2,3,2,1]/9)^3   (separable)

#define NVOX 2197          // 13^3
#define VPAD 2208          // padded halves per volume (16B chunks)
#define NCHUNK 276         // VPAD/8
#define NMAX 10000
#define KNN  8
#define XCH_SIZE (19*17*17)
#define NT 608             // 32 x 19

__device__ __half g_S1[(size_t)NMAX * VPAD];
__device__ __half g_S2[(size_t)NMAX * VPAD];

__device__ __forceinline__ __half2 h2shfl_down(__half2 v, unsigned d) {
    unsigned u = *reinterpret_cast<unsigned*>(&v);
    u = __shfl_down_sync(0xFFFFFFFFu, u, d);
    return *reinterpret_cast<__half2*>(&u);
}
__device__ __forceinline__ __half2 hmax3(__half2 a, __half2 b, __half2 c) {
    return __hmax2(__hmax2(a, b), c);
}

// blockDim=(32,19). lx = padded-x lane (valid 0..18), ly = padded-y.
// Each thread holds 19 padded-z half2 values (2 volumes) in registers.
// z passes: registers. x passes: shuffles. y passes: smem. Out -> outb[z*169+y*13+x].
__device__ __forceinline__ void smooth_core_h2(__half2 col[19], __half2* xch,
                                               __half2* outb, int lx, int ly) {
    const __half2 T2 = __float2half2_rn(2.0f);
    const __half2 T3 = __float2half2_rn(3.0f);
    const __half2 INV = __float2half2_rn(1.0f/729.0f);

    __half2 a[17];
    #pragma unroll
    for (int z = 0; z < 17; z++) a[z] = hmax3(col[z], col[z+1], col[z+2]);

    #pragma unroll
    for (int z = 0; z < 17; z++) {
        __half2 n1 = h2shfl_down(a[z], 1);
        __half2 n2 = h2shfl_down(a[z], 2);
        a[z] = hmax3(a[z], n1, n2);
    }

    if (lx < 17) {
        #pragma unroll
        for (int z = 0; z < 17; z++) xch[(ly*17 + z)*17 + lx] = a[z];
    }
    __syncthreads();
    __half2 b[17];
    if (lx < 17 && ly < 17) {
        #pragma unroll
        for (int z = 0; z < 17; z++) {
            __half2 n1 = xch[((ly+1)*17 + z)*17 + lx];
            __half2 n2 = xch[((ly+2)*17 + z)*17 + lx];
            b[z] = hmax3(a[z], n1, n2);
        }
    } else {
        #pragma unroll
        for (int z = 0; z < 17; z++) b[z] = __float2half2_rn(0.0f);
    }

    // 5-tap over z
    __half2 c[13];
    #pragma unroll
    for (int z = 0; z < 13; z++) {
        __half2 t = __hadd2(b[z], b[z+4]);
        t = __hfma2(T2, __hadd2(b[z+1], b[z+3]), t);
        c[z] = __hfma2(T3, b[z+2], t);
    }

    // 5-tap over x
    #pragma unroll
    for (int z = 0; z < 13; z++) {
        __half2 s1 = h2shfl_down(c[z], 1);
        __half2 s2 = h2shfl_down(c[z], 2);
        __half2 s3 = h2shfl_down(c[z], 3);
        __half2 s4 = h2shfl_down(c[z], 4);
        __half2 t = __hadd2(c[z], s4);
        t = __hfma2(T2, __hadd2(s1, s3), t);
        c[z] = __hfma2(T3, s2, t);
    }

    // 5-tap over y via smem
    __syncthreads();
    if (lx < 13 && ly < 17) {
        #pragma unroll
        for (int z = 0; z < 13; z++) xch[(ly*13 + z)*13 + lx] = c[z];
    }
    __syncthreads();
    if (lx < 13 && ly < 13) {
        #pragma unroll
        for (int z = 0; z < 13; z++) {
            __half2 s1 = xch[((ly+1)*13 + z)*13 + lx];
            __half2 s2 = xch[((ly+2)*13 + z)*13 + lx];
            __half2 s3 = xch[((ly+3)*13 + z)*13 + lx];
            __half2 s4 = xch[((ly+4)*13 + z)*13 + lx];
            __half2 t = __hadd2(c[z], s4);
            t = __hfma2(T2, __hadd2(s1, s3), t);
            t = __hfma2(T3, s2, t);
            outb[z*169 + ly*13 + lx] = __hmul2(t, INV);
        }
    }
}

// split paired outb -> per-volume half scratch (half2 stores, pad zeros)
__device__ __forceinline__ void store_pair(const __half2* outb, __half* d0, __half* d1,
                                           int tid) {
    const __half2 Z = __float2half2_rn(0.0f);
    for (int i = tid; i < VPAD/2; i += NT) {
        int i0 = 2*i;
        __half2 v0 = (i0     < NVOX) ? outb[i0]     : Z;
        __half2 v1 = (i0 + 1 < NVOX) ? outb[i0 + 1] : Z;
        *reinterpret_cast<__half2*>(d0 + i0) = __lows2half2(v0, v1);
        *reinterpret_cast<__half2*>(d1 + i0) = __highs2half2(v0, v1);
    }
}

// ---------------- Kernel A: S1 = smooth(a1 + a0*cost), paired ----------------
__global__ void __launch_bounds__(NT) k_smooth1(
    const float* __restrict__ cost, const float* __restrict__ alpha) {
    __shared__ __half2 xch[XCH_SIZE];
    __shared__ __half2 outb[NVOX];
    __shared__ __half2 inb[NVOX];
    int p = blockIdx.x;
    int lx = threadIdx.x, ly = threadIdx.y;
    int tid = ly*32 + lx;
    float a0 = alpha[0], a1 = alpha[1];
    const float* s0 = cost + (size_t)(2*p) * NVOX;
    const float* s1 = cost + (size_t)(2*p + 1) * NVOX;

    for (int i = tid; i < NVOX; i += NT)
        inb[i] = __floats2half2_rn(a1 + a0 * __ldg(s0 + i), a1 + a0 * __ldg(s1 + i));
    __syncthreads();

    int cx = min(max(lx - 3, 0), 12);
    int cy = min(max(ly - 3, 0), 12);
    __half2 col[19];
    #pragma unroll
    for (int z = 0; z < 19; z++) {
        int cz = min(max(z - 3, 0), 12);
        col[z] = inb[cz*169 + cy*13 + cx];
    }
    smooth_core_h2(col, xch, outb, lx, ly);
    __syncthreads();
    store_pair(outb, g_S1 + (size_t)(2*p)*VPAD, g_S1 + (size_t)(2*p+1)*VPAD, tid);
}

// ------- Kernel B: c2 = blend(cost, gatherW(S1)); S2 = smooth(c2), paired -------
__global__ void __launch_bounds__(NT) k_gather_smooth(
    const float* __restrict__ cost, const int* __restrict__ knn,
    const float* __restrict__ dist, const float* __restrict__ alpha) {
    __shared__ __half2 xch[XCH_SIZE];
    __shared__ __half2 outb[NVOX];
    __shared__ __half2 c2[NVOX];
    __shared__ float wsh[2][KNN];
    __shared__ int   nbsh[2][KNN];
    __shared__ float sninv[2];
    int p = blockIdx.x;
    int lx = threadIdx.x, ly = threadIdx.y;
    int tid = ly*32 + lx;

    if (tid < 2) {
        int n = 2*p + tid;
        float s = 0.0f;
        #pragma unroll
        for (int k = 0; k < KNN; k++) {
            float w = expf(-__ldg(&dist[n*KNN + k]) * (1.0f/200.0f));  // 2*SIGMA^2=200
            wsh[tid][k] = w; s += w;
            nbsh[tid][k] = __ldg(&knn[n*KNN + k]);
        }
        sninv[tid] = 1.0f / s;
    }
    __syncthreads();

    float a0 = alpha[0], a1 = alpha[1], a2 = alpha[2], a3 = alpha[3], a4 = alpha[4];

    if (tid < NCHUNK) {
        int cch = tid;
        int vbase = cch * 8;
        float res[2][8];
        #pragma unroll
        for (int h = 0; h < 2; h++) {
            float acc[8];
            #pragma unroll
            for (int j = 0; j < 8; j++) acc[j] = 0.0f;
            #pragma unroll
            for (int k = 0; k < KNN; k++) {
                float w = wsh[h][k];
                const uint4* np = reinterpret_cast<const uint4*>(
                    g_S1 + (size_t)nbsh[h][k] * VPAD);
                uint4 raw = __ldg(&np[cch]);
                __half2 h0 = *reinterpret_cast<__half2*>(&raw.x);
                __half2 h1 = *reinterpret_cast<__half2*>(&raw.y);
                __half2 h2 = *reinterpret_cast<__half2*>(&raw.z);
                __half2 h3 = *reinterpret_cast<__half2*>(&raw.w);
                float2 f0 = __half22float2(h0), f1 = __half22float2(h1);
                float2 f2 = __half22float2(h2), f3 = __half22float2(h3);
                acc[0] += w*f0.x; acc[1] += w*f0.y;
                acc[2] += w*f1.x; acc[3] += w*f1.y;
                acc[4] += w*f2.x; acc[5] += w*f2.y;
                acc[6] += w*f3.x; acc[7] += w*f3.y;
            }
            const float* src = cost + (size_t)(2*p + h) * NVOX;
            float ninv = sninv[h];
            #pragma unroll
            for (int j = 0; j < 8; j++) {
                int v = vbase + j;
                float c1 = (v < NVOX) ? (a1 + a0 * __ldg(&src[v])) : 0.0f;
                res[h][j] = a4 + a2*c1 + a3*(acc[j]*ninv);
            }
        }
        #pragma unroll
        for (int j = 0; j < 8; j++) {
            int v = vbase + j;
            if (v < NVOX) c2[v] = __floats2half2_rn(res[0][j], res[1][j]);
        }
    }
    __syncthreads();

    int cx = min(max(lx - 3, 0), 12);
    int cy = min(max(ly - 3, 0), 12);
    __half2 col[19];
    #pragma unroll
    for (int z = 0; z < 19; z++) {
        int cz = min(max(z - 3, 0), 12);
        col[z] = c2[cz*169 + cy*13 + cx];
    }
    smooth_core_h2(col, xch, outb, lx, ly);
    __syncthreads();
    store_pair(outb, g_S2 + (size_t)(2*p)*VPAD, g_S2 + (size_t)(2*p+1)*VPAD, tid);
}

// ---------------- Kernel C: out = a5 * gatherW(S2) / norm ----------------
__global__ void __launch_bounds__(288) k_gather_out(
    const int* __restrict__ knn, const float* __restrict__ dist,
    const float* __restrict__ alpha, float* __restrict__ out) {
    __shared__ float wsh[KNN];
    __shared__ int   nbsh[KNN];
    __shared__ float sscale;
    int n = blockIdx.x;
    int tid = threadIdx.x;
    if (tid == 0) {
        float s = 0.0f;
        #pragma unroll
        for (int k = 0; k < KNN; k++) {
            float w = expf(-__ldg(&dist[n*KNN + k]) * (1.0f/200.0f));
            wsh[k] = w; s += w;
            nbsh[k] = __ldg(&knn[n*KNN + k]);
        }
        sscale = alpha[5] / s;
    }
    __syncthreads();
    if (tid < NCHUNK) {
        int cch = tid;
        float sc = sscale;
        float acc[8];
        #pragma unroll
        for (int j = 0; j < 8; j++) acc[j] = 0.0f;
        #pragma unroll
        for (int k = 0; k < KNN; k++) {
            float w = wsh[k];
            const uint4* np = reinterpret_cast<const uint4*>(
                g_S2 + (size_t)nbsh[k] * VPAD);
            uint4 raw = __ldg(&np[cch]);
            __half2 h0 = *reinterpret_cast<__half2*>(&raw.x);
            __half2 h1 = *reinterpret_cast<__half2*>(&raw.y);
            __half2 h2 = *reinterpret_cast<__half2*>(&raw.z);
            __half2 h3 = *reinterpret_cast<__half2*>(&raw.w);
            float2 f0 = __half22float2(h0), f1 = __half22float2(h1);
            float2 f2 = __half22float2(h2), f3 = __half22float2(h3);
            acc[0] += w*f0.x; acc[1] += w*f0.y;
            acc[2] += w*f1.x; acc[3] += w*f1.y;
            acc[4] += w*f2.x; acc[5] += w*f2.y;
            acc[6] += w*f3.x; acc[7] += w*f3.y;
        }
        float* dst = out + (size_t)n * NVOX;
        int vbase = cch * 8;
        #pragma unroll
        for (int j = 0; j < 8; j++) {
            int v = vbase + j;
            if (v < NVOX) dst[v] = acc[j] * sc;
        }
    }
}

extern "C" void kernel_launch(void* const* d_in, const int* in_sizes, int n_in,
                              void* d_out, int out_size) {
    const float* cost  = (const float*)d_in[0];
    const int*   knn   = (const int*)d_in[1];
    const float* dist  = (const float*)d_in[2];
    const float* alpha = (const float*)d_in[3];
    float* out = (float*)d_out;
    int N = in_sizes[0] / NVOX;   // 10000
    int NP = N / 2;               // 5000 volume pairs

    dim3 blk(32, 19);
    k_smooth1<<<NP, blk>>>(cost, alpha);
    k_gather_smooth<<<NP, blk>>>(cost, knn, dist, alpha);
    k_gather_out<<<N, 288>>>(knn, dist, alpha, out);
}

// round 6
// speedup vs baseline: 2.0399x; 1.0590x over previous
#include <cuda_runtime.h>
#include <cuda_fp16.h>

// deeds_graph: N=10000 volumes of 13^3, K=8 neighbors. Volume-paired half2 pipeline.
// S1 = smooth(a1 + a0*cost); c2 = a4 + a2*(a1+a0*cost) + a3*gatherW(S1)/norm;
// S2 = smooth(c2); out = a5*gatherW(S2)/norm.
// smooth = edge-pad(3) -> max3^3 -> (5-tap [1,2,3,2,1]/9)^3 (separable).

#define NVOX 2197          // 13^3
#define VPAD 2208          // padded halves per volume (16B chunks)
#define NCHUNK 276         // VPAD/8
#define NMAX 10000
#define KNN  8
#define XCH_SIZE (19*17*17)
#define NT 608             // 32 x 19
#define CT 576             // kernel C block

__device__ __half g_S1[(size_t)NMAX * VPAD];
__device__ __half g_S2[(size_t)NMAX * VPAD];

__device__ __forceinline__ __half2 h2shfl_down(__half2 v, unsigned d) {
    unsigned u = *reinterpret_cast<unsigned*>(&v);
    u = __shfl_down_sync(0xFFFFFFFFu, u, d);
    return *reinterpret_cast<__half2*>(&u);
}
__device__ __forceinline__ __half2 hmax3(__half2 a, __half2 b, __half2 c) {
    return __hmax2(__hmax2(a, b), c);
}

// blockDim=(32,19). lx = padded-x lane (valid 0..18), ly = padded-y.
// z passes: registers. x passes: shuffles. y passes: smem.
__device__ __forceinline__ void smooth_core_h2(__half2 col[19], __half2* xch,
                                               __half2* outb, int lx, int ly) {
    const __half2 T2 = __float2half2_rn(2.0f);
    const __half2 T3 = __float2half2_rn(3.0f);
    const __half2 INV = __float2half2_rn(1.0f/729.0f);

    __half2 a[17];
    #pragma unroll
    for (int z = 0; z < 17; z++) a[z] = hmax3(col[z], col[z+1], col[z+2]);

    #pragma unroll
    for (int z = 0; z < 17; z++) {
        __half2 n1 = h2shfl_down(a[z], 1);
        __half2 n2 = h2shfl_down(a[z], 2);
        a[z] = hmax3(a[z], n1, n2);
    }

    if (lx < 17) {
        #pragma unroll
        for (int z = 0; z < 17; z++) xch[(ly*17 + z)*17 + lx] = a[z];
    }
    __syncthreads();
    __half2 b[17];
    if (lx < 17 && ly < 17) {
        #pragma unroll
        for (int z = 0; z < 17; z++) {
            __half2 n1 = xch[((ly+1)*17 + z)*17 + lx];
            __half2 n2 = xch[((ly+2)*17 + z)*17 + lx];
            b[z] = hmax3(a[z], n1, n2);
        }
    } else {
        #pragma unroll
        for (int z = 0; z < 17; z++) b[z] = __float2half2_rn(0.0f);
    }

    __half2 c[13];
    #pragma unroll
    for (int z = 0; z < 13; z++) {
        __half2 t = __hadd2(b[z], b[z+4]);
        t = __hfma2(T2, __hadd2(b[z+1], b[z+3]), t);
        c[z] = __hfma2(T3, b[z+2], t);
    }

    #pragma unroll
    for (int z = 0; z < 13; z++) {
        __half2 s1 = h2shfl_down(c[z], 1);
        __half2 s2 = h2shfl_down(c[z], 2);
        __half2 s3 = h2shfl_down(c[z], 3);
        __half2 s4 = h2shfl_down(c[z], 4);
        __half2 t = __hadd2(c[z], s4);
        t = __hfma2(T2, __hadd2(s1, s3), t);
        c[z] = __hfma2(T3, s2, t);
    }

    __syncthreads();
    if (lx < 13 && ly < 17) {
        #pragma unroll
        for (int z = 0; z < 13; z++) xch[(ly*13 + z)*13 + lx] = c[z];
    }
    __syncthreads();
    if (lx < 13 && ly < 13) {
        #pragma unroll
        for (int z = 0; z < 13; z++) {
            __half2 s1 = xch[((ly+1)*13 + z)*13 + lx];
            __half2 s2 = xch[((ly+2)*13 + z)*13 + lx];
            __half2 s3 = xch[((ly+3)*13 + z)*13 + lx];
            __half2 s4 = xch[((ly+4)*13 + z)*13 + lx];
            __half2 t = __hadd2(c[z], s4);
            t = __hfma2(T2, __hadd2(s1, s3), t);
            t = __hfma2(T3, s2, t);
            outb[z*169 + ly*13 + lx] = __hmul2(t, INV);
        }
    }
}

__device__ __forceinline__ void store_pair(const __half2* outb, __half* d0, __half* d1,
                                           int tid) {
    const __half2 Z = __float2half2_rn(0.0f);
    for (int i = tid; i < VPAD/2; i += NT) {
        int i0 = 2*i;
        __half2 v0 = (i0     < NVOX) ? outb[i0]     : Z;
        __half2 v1 = (i0 + 1 < NVOX) ? outb[i0 + 1] : Z;
        *reinterpret_cast<__half2*>(d0 + i0) = __lows2half2(v0, v1);
        *reinterpret_cast<__half2*>(d1 + i0) = __highs2half2(v0, v1);
    }
}

// ---------------- Kernel A: S1 = smooth(a1 + a0*cost), paired ----------------
__global__ void __launch_bounds__(NT) k_smooth1(
    const float* __restrict__ cost, const float* __restrict__ alpha) {
    __shared__ __half2 xch[XCH_SIZE];
    __shared__ __half2 outb[NVOX];
    __shared__ __half2 inb[NVOX];
    int p = blockIdx.x;
    int lx = threadIdx.x, ly = threadIdx.y;
    int tid = ly*32 + lx;
    float a0 = alpha[0], a1 = alpha[1];
    const float* s0 = cost + (size_t)(2*p) * NVOX;
    const float* s1 = cost + (size_t)(2*p + 1) * NVOX;

    for (int i = tid; i < NVOX; i += NT)
        inb[i] = __floats2half2_rn(a1 + a0 * __ldg(s0 + i), a1 + a0 * __ldg(s1 + i));
    __syncthreads();

    int cx = min(max(lx - 3, 0), 12);
    int cy = min(max(ly - 3, 0), 12);
    __half2 col[19];
    #pragma unroll
    for (int z = 0; z < 19; z++) {
        int cz = min(max(z - 3, 0), 12);
        col[z] = inb[cz*169 + cy*13 + cx];
    }
    smooth_core_h2(col, xch, outb, lx, ly);
    __syncthreads();
    store_pair(outb, g_S1 + (size_t)(2*p)*VPAD, g_S1 + (size_t)(2*p+1)*VPAD, tid);
}

// ------- Kernel B: c2 = blend(cost, gatherW(S1)); S2 = smooth(c2), paired -------
__global__ void __launch_bounds__(NT) k_gather_smooth(
    const float* __restrict__ cost, const int* __restrict__ knn,
    const float* __restrict__ dist, const float* __restrict__ alpha) {
    __shared__ __half2 xch[XCH_SIZE];
    __shared__ __half2 outb[NVOX];
    __shared__ __half2 c2[NVOX];
    __shared__ float wsh[2][KNN];
    __shared__ int   nbsh[2][KNN];
    __shared__ float sninv[2];
    int p = blockIdx.x;
    int lx = threadIdx.x, ly = threadIdx.y;
    int tid = ly*32 + lx;

    if (tid < 16) {                       // parallel weight compute
        int h = tid >> 3, k = tid & 7;
        int n = 2*p + h;
        wsh[h][k] = __expf(-__ldg(&dist[n*KNN + k]) * (1.0f/200.0f)); // 2*SIGMA^2=200
        nbsh[h][k] = __ldg(&knn[n*KNN + k]);
    }
    __syncthreads();
    if (tid < 2) {
        float s = 0.0f;
        #pragma unroll
        for (int k = 0; k < KNN; k++) s += wsh[tid][k];
        sninv[tid] = 1.0f / s;
    }
    __syncthreads();

    float a0 = alpha[0], a1 = alpha[1], a2 = alpha[2], a3 = alpha[3], a4 = alpha[4];

    if (tid < NCHUNK) {
        int cch = tid;
        int vbase = cch * 8;
        float res[2][8];
        #pragma unroll
        for (int h = 0; h < 2; h++) {
            float acc[8];
            #pragma unroll
            for (int j = 0; j < 8; j++) acc[j] = 0.0f;
            #pragma unroll
            for (int k = 0; k < KNN; k++) {
                float w = wsh[h][k];
                const uint4* np = reinterpret_cast<const uint4*>(
                    g_S1 + (size_t)nbsh[h][k] * VPAD);
                uint4 raw = __ldg(&np[cch]);
                __half2 h0 = *reinterpret_cast<__half2*>(&raw.x);
                __half2 h1 = *reinterpret_cast<__half2*>(&raw.y);
                __half2 h2 = *reinterpret_cast<__half2*>(&raw.z);
                __half2 h3 = *reinterpret_cast<__half2*>(&raw.w);
                float2 f0 = __half22float2(h0), f1 = __half22float2(h1);
                float2 f2 = __half22float2(h2), f3 = __half22float2(h3);
                acc[0] += w*f0.x; acc[1] += w*f0.y;
                acc[2] += w*f1.x; acc[3] += w*f1.y;
                acc[4] += w*f2.x; acc[5] += w*f2.y;
                acc[6] += w*f3.x; acc[7] += w*f3.y;
            }
            const float* src = cost + (size_t)(2*p + h) * NVOX;
            float ninv = sninv[h];
            #pragma unroll
            for (int j = 0; j < 8; j++) {
                int v = vbase + j;
                float c1 = (v < NVOX) ? (a1 + a0 * __ldg(&src[v])) : 0.0f;
                res[h][j] = a4 + a2*c1 + a3*(acc[j]*ninv);
            }
        }
        #pragma unroll
        for (int j = 0; j < 8; j++) {
            int v = vbase + j;
            if (v < NVOX) c2[v] = __floats2half2_rn(res[0][j], res[1][j]);
        }
    }
    __syncthreads();

    int cx = min(max(lx - 3, 0), 12);
    int cy = min(max(ly - 3, 0), 12);
    __half2 col[19];
    #pragma unroll
    for (int z = 0; z < 19; z++) {
        int cz = min(max(z - 3, 0), 12);
        col[z] = c2[cz*169 + cy*13 + cx];
    }
    smooth_core_h2(col, xch, outb, lx, ly);
    __syncthreads();
    store_pair(outb, g_S2 + (size_t)(2*p)*VPAD, g_S2 + (size_t)(2*p+1)*VPAD, tid);
}

// ------- Kernel C: out = a5 * gatherW(S2) / norm, paired + coalesced stores -------
__global__ void __launch_bounds__(CT) k_gather_out(
    const int* __restrict__ knn, const float* __restrict__ dist,
    const float* __restrict__ alpha, float* __restrict__ out) {
    __shared__ float wsh[2][KNN];
    __shared__ int   nbsh[2][KNN];
    __shared__ float sscale[2];
    __shared__ float obuf[2][VPAD];
    int p = blockIdx.x;
    int tid = threadIdx.x;

    if (tid < 16) {
        int h = tid >> 3, k = tid & 7;
        int n = 2*p + h;
        wsh[h][k] = __expf(-__ldg(&dist[n*KNN + k]) * (1.0f/200.0f));
        nbsh[h][k] = __ldg(&knn[n*KNN + k]);
    }
    __syncthreads();
    if (tid < 2) {
        float s = 0.0f;
        #pragma unroll
        for (int k = 0; k < KNN; k++) s += wsh[tid][k];
        sscale[tid] = alpha[5] / s;
    }
    __syncthreads();

    if (tid < 2*NCHUNK) {
        int h = tid / NCHUNK;
        int cch = tid - h*NCHUNK;
        float acc[8];
        #pragma unroll
        for (int j = 0; j < 8; j++) acc[j] = 0.0f;
        #pragma unroll
        for (int k = 0; k < KNN; k++) {
            float w = wsh[h][k];
            const uint4* np = reinterpret_cast<const uint4*>(
                g_S2 + (size_t)nbsh[h][k] * VPAD);
            uint4 raw = __ldg(&np[cch]);
            __half2 h0 = *reinterpret_cast<__half2*>(&raw.x);
            __half2 h1 = *reinterpret_cast<__half2*>(&raw.y);
            __half2 h2 = *reinterpret_cast<__half2*>(&raw.z);
            __half2 h3 = *reinterpret_cast<__half2*>(&raw.w);
            float2 f0 = __half22float2(h0), f1 = __half22float2(h1);
            float2 f2 = __half22float2(h2), f3 = __half22float2(h3);
            acc[0] += w*f0.x; acc[1] += w*f0.y;
            acc[2] += w*f1.x; acc[3] += w*f1.y;
            acc[4] += w*f2.x; acc[5] += w*f2.y;
            acc[6] += w*f3.x; acc[7] += w*f3.y;
        }
        float sc = sscale[h];
        int vbase = cch * 8;
        #pragma unroll
        for (int j = 0; j < 8; j++) obuf[h][vbase + j] = acc[j] * sc;
    }
    __syncthreads();

    float* d0 = out + (size_t)(2*p) * NVOX;
    float* d1 = out + (size_t)(2*p + 1) * NVOX;
    for (int i = tid; i < NVOX; i += CT) {
        d0[i] = obuf[0][i];
        d1[i] = obuf[1][i];
    }
}

extern "C" void kernel_launch(void* const* d_in, const int* in_sizes, int n_in,
                              void* d_out, int out_size) {
    const float* cost  = (const float*)d_in[0];
    const int*   knn   = (const int*)d_in[1];
    const float* dist  = (const float*)d_in[2];
    const float* alpha = (const float*)d_in[3];
    float* out = (float*)d_out;
    int N = in_sizes[0] / NVOX;   // 10000
    int NP = N / 2;               // 5000 volume pairs

    dim3 blk(32, 19);
    k_smooth1<<<NP, blk>>>(cost, alpha);
    k_gather_smooth<<<NP, blk>>>(cost, knn, dist, alpha);
    k_gather_out<<<NP, CT>>>(knn, dist, alpha, out);
}

// round 7
// speedup vs baseline: 2.3994x; 1.1762x over previous
#include <cuda_runtime.h>
#include <cuda_fp16.h>

// deeds_graph: N=10000 volumes of 13^3, K=8 neighbors. Volume-paired half2 pipeline.
// S1 = smooth(a1 + a0*cost); c2 = a4 + a2*(a1+a0*cost) + a3*gatherW(S1)/norm;
// S2 = smooth(c2); out = a5*gatherW(S2)/norm.
// smooth = edge-pad(3) -> max3^3 -> (5-tap [1,2,3,2,1]/9)^3 (separable).
// y-pass smem exchange is vectorized: rows are z-contiguous, stride 20 half2 (80B)
// -> 16B-aligned LDS.128/STS.128, conflict-free (16B-group = lane*5 mod 8).

#define NVOX 2197          // 13^3
#define VPAD 2208          // padded halves per volume (16B chunks)
#define NCHUNK 276         // VPAD/8
#define NMAX 10000
#define KNN  8
#define XROW 20            // half2 words per exchange row (80B, 16B-aligned, conflict-free)
#define XCH_H2 (19*17*XROW)
#define NT 608             // 32 x 19
#define CT 576             // kernel C block

__device__ __half g_S1[(size_t)NMAX * VPAD];
__device__ __half g_S2[(size_t)NMAX * VPAD];

__device__ __forceinline__ unsigned h2u(__half2 v) { return *reinterpret_cast<unsigned*>(&v); }
__device__ __forceinline__ __half2 u2h(unsigned u) { return *reinterpret_cast<__half2*>(&u); }
__device__ __forceinline__ uint4 pk4(__half2 a, __half2 b, __half2 c, __half2 d) {
    return make_uint4(h2u(a), h2u(b), h2u(c), h2u(d));
}
__device__ __forceinline__ __half2 h2shfl_down(__half2 v, unsigned d) {
    return u2h(__shfl_down_sync(0xFFFFFFFFu, h2u(v), d));
}
__device__ __forceinline__ __half2 hmax3(__half2 a, __half2 b, __half2 c) {
    return __hmax2(__hmax2(a, b), c);
}

__device__ __forceinline__ void load_row17(const __half2* base, __half2 r[17]) {
    const uint4* p = reinterpret_cast<const uint4*>(base);
    uint4 v0 = p[0], v1 = p[1], v2 = p[2], v3 = p[3];
    unsigned w = reinterpret_cast<const unsigned*>(base)[16];
    r[0]=u2h(v0.x); r[1]=u2h(v0.y); r[2]=u2h(v0.z); r[3]=u2h(v0.w);
    r[4]=u2h(v1.x); r[5]=u2h(v1.y); r[6]=u2h(v1.z); r[7]=u2h(v1.w);
    r[8]=u2h(v2.x); r[9]=u2h(v2.y); r[10]=u2h(v2.z); r[11]=u2h(v2.w);
    r[12]=u2h(v3.x); r[13]=u2h(v3.y); r[14]=u2h(v3.z); r[15]=u2h(v3.w);
    r[16]=u2h(w);
}
__device__ __forceinline__ void load_row13(const __half2* base, __half2 r[13]) {
    const uint4* p = reinterpret_cast<const uint4*>(base);
    uint4 v0 = p[0], v1 = p[1], v2 = p[2];
    unsigned w = reinterpret_cast<const unsigned*>(base)[12];
    r[0]=u2h(v0.x); r[1]=u2h(v0.y); r[2]=u2h(v0.z); r[3]=u2h(v0.w);
    r[4]=u2h(v1.x); r[5]=u2h(v1.y); r[6]=u2h(v1.z); r[7]=u2h(v1.w);
    r[8]=u2h(v2.x); r[9]=u2h(v2.y); r[10]=u2h(v2.z); r[11]=u2h(v2.w);
    r[12]=u2h(w);
}

// blockDim=(32,19). lx = padded-x lane (valid 0..18), ly = padded-y.
// z passes: registers. x passes: shuffles. y passes: vectorized smem rows.
__device__ __forceinline__ void smooth_core_h2(__half2 col[19], __half2* xch,
                                               __half2* outb, int lx, int ly) {
    const __half2 T2 = __float2half2_rn(2.0f);
    const __half2 T3 = __float2half2_rn(3.0f);
    const __half2 INV = __float2half2_rn(1.0f/729.0f);

    // max over z (registers)
    __half2 a[17];
    #pragma unroll
    for (int z = 0; z < 17; z++) a[z] = hmax3(col[z], col[z+1], col[z+2]);

    // max over x (shuffles)
    #pragma unroll
    for (int z = 0; z < 17; z++) {
        __half2 n1 = h2shfl_down(a[z], 1);
        __half2 n2 = h2shfl_down(a[z], 2);
        a[z] = hmax3(a[z], n1, n2);
    }

    // max over y: vectorized rows [(ly*17+lx)*XROW], 17 words each
    if (lx < 17) {
        uint4* row = reinterpret_cast<uint4*>(xch + (ly*17 + lx)*XROW);
        row[0] = pk4(a[0], a[1], a[2], a[3]);
        row[1] = pk4(a[4], a[5], a[6], a[7]);
        row[2] = pk4(a[8], a[9], a[10], a[11]);
        row[3] = pk4(a[12], a[13], a[14], a[15]);
        reinterpret_cast<unsigned*>(row)[16] = h2u(a[16]);
    }
    __syncthreads();
    if (lx < 17 && ly < 17) {
        __half2 r[17];
        load_row17(xch + ((ly+1)*17 + lx)*XROW, r);
        #pragma unroll
        for (int z = 0; z < 17; z++) a[z] = __hmax2(a[z], r[z]);
        load_row17(xch + ((ly+2)*17 + lx)*XROW, r);
        #pragma unroll
        for (int z = 0; z < 17; z++) a[z] = __hmax2(a[z], r[z]);
    }

    // 5-tap over z (registers)
    __half2 c[13];
    #pragma unroll
    for (int z = 0; z < 13; z++) {
        __half2 t = __hadd2(a[z], a[z+4]);
        t = __hfma2(T2, __hadd2(a[z+1], a[z+3]), t);
        c[z] = __hfma2(T3, a[z+2], t);
    }

    // 5-tap over x (shuffles)
    #pragma unroll
    for (int z = 0; z < 13; z++) {
        __half2 s1 = h2shfl_down(c[z], 1);
        __half2 s2 = h2shfl_down(c[z], 2);
        __half2 s3 = h2shfl_down(c[z], 3);
        __half2 s4 = h2shfl_down(c[z], 4);
        __half2 t = __hadd2(c[z], s4);
        t = __hfma2(T2, __hadd2(s1, s3), t);
        c[z] = __hfma2(T3, s2, t);
    }

    // 5-tap over y: vectorized rows [(ly*13+lx)*XROW], 13 words each
    __syncthreads();
    if (lx < 13 && ly < 17) {
        uint4* row = reinterpret_cast<uint4*>(xch + (ly*13 + lx)*XROW);
        row[0] = pk4(c[0], c[1], c[2], c[3]);
        row[1] = pk4(c[4], c[5], c[6], c[7]);
        row[2] = pk4(c[8], c[9], c[10], c[11]);
        reinterpret_cast<unsigned*>(row)[12] = h2u(c[12]);
    }
    __syncthreads();
    if (lx < 13 && ly < 13) {
        __half2 r[13];
        load_row13(xch + ((ly+4)*13 + lx)*XROW, r);
        #pragma unroll
        for (int z = 0; z < 13; z++) c[z] = __hadd2(c[z], r[z]);
        load_row13(xch + ((ly+1)*13 + lx)*XROW, r);
        #pragma unroll
        for (int z = 0; z < 13; z++) c[z] = __hfma2(T2, r[z], c[z]);
        load_row13(xch + ((ly+3)*13 + lx)*XROW, r);
        #pragma unroll
        for (int z = 0; z < 13; z++) c[z] = __hfma2(T2, r[z], c[z]);
        load_row13(xch + ((ly+2)*13 + lx)*XROW, r);
        #pragma unroll
        for (int z = 0; z < 13; z++) c[z] = __hfma2(T3, r[z], c[z]);
        #pragma unroll
        for (int z = 0; z < 13; z++)
            outb[z*169 + ly*13 + lx] = __hmul2(c[z], INV);
    }
}

__device__ __forceinline__ void store_pair(const __half2* outb, __half* d0, __half* d1,
                                           int tid) {
    const __half2 Z = __float2half2_rn(0.0f);
    for (int i = tid; i < VPAD/2; i += NT) {
        int i0 = 2*i;
        __half2 v0 = (i0     < NVOX) ? outb[i0]     : Z;
        __half2 v1 = (i0 + 1 < NVOX) ? outb[i0 + 1] : Z;
        *reinterpret_cast<__half2*>(d0 + i0) = __lows2half2(v0, v1);
        *reinterpret_cast<__half2*>(d1 + i0) = __highs2half2(v0, v1);
    }
}

// ---------------- Kernel A: S1 = smooth(a1 + a0*cost), paired ----------------
__global__ void __launch_bounds__(NT) k_smooth1(
    const float* __restrict__ cost, const float* __restrict__ alpha) {
    __shared__ __align__(16) __half2 xch[XCH_H2];
    __shared__ __half2 outb[NVOX];
    __shared__ __half2 inb[NVOX];
    int p = blockIdx.x;
    int lx = threadIdx.x, ly = threadIdx.y;
    int tid = ly*32 + lx;
    float a0 = alpha[0], a1 = alpha[1];
    const float* s0 = cost + (size_t)(2*p) * NVOX;
    const float* s1 = cost + (size_t)(2*p + 1) * NVOX;

    for (int i = tid; i < NVOX; i += NT)
        inb[i] = __floats2half2_rn(a1 + a0 * __ldg(s0 + i), a1 + a0 * __ldg(s1 + i));
    __syncthreads();

    int cx = min(max(lx - 3, 0), 12);
    int cy = min(max(ly - 3, 0), 12);
    __half2 col[19];
    #pragma unroll
    for (int z = 0; z < 19; z++) {
        int cz = min(max(z - 3, 0), 12);
        col[z] = inb[cz*169 + cy*13 + cx];
    }
    smooth_core_h2(col, xch, outb, lx, ly);
    __syncthreads();
    store_pair(outb, g_S1 + (size_t)(2*p)*VPAD, g_S1 + (size_t)(2*p+1)*VPAD, tid);
}

// ------- Kernel B: c2 = blend(cost, gatherW(S1)); S2 = smooth(c2), paired -------
__global__ void __launch_bounds__(NT) k_gather_smooth(
    const float* __restrict__ cost, const int* __restrict__ knn,
    const float* __restrict__ dist, const float* __restrict__ alpha) {
    __shared__ __align__(16) __half2 xch[XCH_H2];
    __shared__ __half2 outb[NVOX];
    __shared__ __half2 c2[VPAD];          // interleaved: half element 2*v+h
    __shared__ float wsh[2][KNN];
    __shared__ int   nbsh[2][KNN];
    __shared__ float sninv[2];
    int p = blockIdx.x;
    int lx = threadIdx.x, ly = threadIdx.y;
    int tid = ly*32 + lx;

    if (tid < 16) {
        int h = tid >> 3, k = tid & 7;
        int n = 2*p + h;
        wsh[h][k] = __expf(-__ldg(&dist[n*KNN + k]) * (1.0f/200.0f)); // 2*SIGMA^2=200
        nbsh[h][k] = __ldg(&knn[n*KNN + k]);
    }
    __syncthreads();
    if (tid < 2) {
        float s = 0.0f;
        #pragma unroll
        for (int k = 0; k < KNN; k++) s += wsh[tid][k];
        sninv[tid] = 1.0f / s;
    }
    __syncthreads();

    float a0 = alpha[0], a1 = alpha[1], a2 = alpha[2], a3 = alpha[3], a4 = alpha[4];

    // 552 threads: one (volume h, chunk) each, 8 LDG.128 per thread
    if (tid < 2*NCHUNK) {
        int h = tid / NCHUNK;
        int cch = tid - h*NCHUNK;
        int vbase = cch * 8;
        float acc[8];
        #pragma unroll
        for (int j = 0; j < 8; j++) acc[j] = 0.0f;
        #pragma unroll
        for (int k = 0; k < KNN; k++) {
            float w = wsh[h][k];
            const uint4* np = reinterpret_cast<const uint4*>(
                g_S1 + (size_t)nbsh[h][k] * VPAD);
            uint4 raw = __ldg(&np[cch]);
            float2 f0 = __half22float2(u2h(raw.x));
            float2 f1 = __half22float2(u2h(raw.y));
            float2 f2 = __half22float2(u2h(raw.z));
            float2 f3 = __half22float2(u2h(raw.w));
            acc[0] += w*f0.x; acc[1] += w*f0.y;
            acc[2] += w*f1.x; acc[3] += w*f1.y;
            acc[4] += w*f2.x; acc[5] += w*f2.y;
            acc[6] += w*f3.x; acc[7] += w*f3.y;
        }
        const float* src = cost + (size_t)(2*p + h) * NVOX;
        float ninv = sninv[h];
        __half* c2h = reinterpret_cast<__half*>(c2);
        #pragma unroll
        for (int j = 0; j < 8; j++) {
            int v = vbase + j;
            float c1 = (v < NVOX) ? (a1 + a0 * __ldg(&src[v])) : 0.0f;
            c2h[2*v + h] = __float2half_rn(a4 + a2*c1 + a3*(acc[j]*ninv));
        }
    }
    __syncthreads();

    int cx = min(max(lx - 3, 0), 12);
    int cy = min(max(ly - 3, 0), 12);
    __half2 col[19];
    #pragma unroll
    for (int z = 0; z < 19; z++) {
        int cz = min(max(z - 3, 0), 12);
        col[z] = c2[cz*169 + cy*13 + cx];
    }
    smooth_core_h2(col, xch, outb, lx, ly);
    __syncthreads();
    store_pair(outb, g_S2 + (size_t)(2*p)*VPAD, g_S2 + (size_t)(2*p+1)*VPAD, tid);
}

// ------- Kernel C: out = a5 * gatherW(S2) / norm, paired + coalesced stores -------
__global__ void __launch_bounds__(CT) k_gather_out(
    const int* __restrict__ knn, const float* __restrict__ dist,
    const float* __restrict__ alpha, float* __restrict__ out) {
    __shared__ float wsh[2][KNN];
    __shared__ int   nbsh[2][KNN];
    __shared__ float sscale[2];
    __shared__ float obuf[2][VPAD];
    int p = blockIdx.x;
    int tid = threadIdx.x;

    if (tid < 16) {
        int h = tid >> 3, k = tid & 7;
        int n = 2*p + h;
        wsh[h][k] = __expf(-__ldg(&dist[n*KNN + k]) * (1.0f/200.0f));
        nbsh[h][k] = __ldg(&knn[n*KNN + k]);
    }
    __syncthreads();
    if (tid < 2) {
        float s = 0.0f;
        #pragma unroll
        for (int k = 0; k < KNN; k++) s += wsh[tid][k];
        sscale[tid] = alpha[5] / s;
    }
    __syncthreads();

    if (tid < 2*NCHUNK) {
        int h = tid / NCHUNK;
        int cch = tid - h*NCHUNK;
        float acc[8];
        #pragma unroll
        for (int j = 0; j < 8; j++) acc[j] = 0.0f;
        #pragma unroll
        for (int k = 0; k < KNN; k++) {
            float w = wsh[h][k];
            const uint4* np = reinterpret_cast<const uint4*>(
                g_S2 + (size_t)nbsh[h][k] * VPAD);
            uint4 raw = __ldg(&np[cch]);
            float2 f0 = __half22float2(u2h(raw.x));
            float2 f1 = __half22float2(u2h(raw.y));
            float2 f2 = __half22float2(u2h(raw.z));
            float2 f3 = __half22float2(u2h(raw.w));
            acc[0] += w*f0.x; acc[1] += w*f0.y;
            acc[2] += w*f1.x; acc[3] += w*f1.y;
            acc[4] += w*f2.x; acc[5] += w*f2.y;
            acc[6] += w*f3.x; acc[7] += w*f3.y;
        }
        float sc = sscale[h];
        int vbase = cch * 8;
        #pragma unroll
        for (int j = 0; j < 8; j++) obuf[h][vbase + j] = acc[j] * sc;
    }
    __syncthreads();

    float* d0 = out + (size_t)(2*p) * NVOX;
    float* d1 = out + (size_t)(2*p + 1) * NVOX;
    for (int i = tid; i < NVOX; i += CT) {
        d0[i] = obuf[0][i];
        d1[i] = obuf[1][i];
    }
}

extern "C" void kernel_launch(void* const* d_in, const int* in_sizes, int n_in,
                              void* d_out, int out_size) {
    const float* cost  = (const float*)d_in[0];
    const int*   knn   = (const int*)d_in[1];
    const float* dist  = (const float*)d_in[2];
    const float* alpha = (const float*)d_in[3];
    float* out = (float*)d_out;
    int N = in_sizes[0] / NVOX;   // 10000
    int NP = N / 2;               // 5000 volume pairs

    dim3 blk(32, 19);
    k_smooth1<<<NP, blk>>>(cost, alpha);
    k_gather_smooth<<<NP, blk>>>(cost, knn, dist, alpha);
    k_gather_out<<<NP, CT>>>(knn, dist, alpha, out);
}

// round 10
// speedup vs baseline: 2.6122x; 1.0887x over previous
#include <cuda_runtime.h>
#include <cuda_fp16.h>

// deeds_graph: N=10000 volumes of 13^3, K=8 neighbors. Volume-paired half2 pipeline.
// S1 = smooth(a1 + a0*cost); c2 = a4 + a2*(a1+a0*cost) + a3*gatherW(S1)/norm;
// S2 = smooth(c2); out = a5*gatherW(S2)/norm.
// smooth = edge-pad(3) -> max3^3 -> (5-tap [1,2,3,2,1]/9)^3 (separable).
// y-pass smem rows are z-contiguous, stride 20 half2 (80B): 16B-aligned LDS.128/STS.128,
// conflict-free. Loads are FUSED into the combine (1 uint4 temp) to keep regs low.

#define NVOX 2197          // 13^3
#define VPAD 2208          // padded halves per volume (16B chunks)
#define NCHUNK 276         // VPAD/8
#define NMAX 10000
#define KNN  8
#define XROW 20            // half2 words per exchange row (80B)
#define XCH_H2 (19*17*XROW)
#define NT 608             // 32 x 19
#define CT 576             // kernel C block

__device__ __half g_S1[(size_t)NMAX * VPAD];
__device__ __half g_S2[(size_t)NMAX * VPAD];

__device__ __forceinline__ unsigned h2u(__half2 v) { return *reinterpret_cast<unsigned*>(&v); }
__device__ __forceinline__ __half2 u2h(unsigned u) { return *reinterpret_cast<__half2*>(&u); }
__device__ __forceinline__ uint4 pk4(__half2 a, __half2 b, __half2 c, __half2 d) {
    return make_uint4(h2u(a), h2u(b), h2u(c), h2u(d));
}
__device__ __forceinline__ __half2 h2shfl_down(__half2 v, unsigned d) {
    return u2h(__shfl_down_sync(0xFFFFFFFFu, h2u(v), d));
}
__device__ __forceinline__ __half2 hmax3(__half2 a, __half2 b, __half2 c) {
    return __hmax2(__hmax2(a, b), c);
}

// fused row combiners: one uint4 temp, accumulate in place
__device__ __forceinline__ void maxrow17(__half2 a[17], const __half2* base) {
    const uint4* p = reinterpret_cast<const uint4*>(base);
    uint4 v;
    v = p[0];
    a[0]=__hmax2(a[0],u2h(v.x)); a[1]=__hmax2(a[1],u2h(v.y));
    a[2]=__hmax2(a[2],u2h(v.z)); a[3]=__hmax2(a[3],u2h(v.w));
    v = p[1];
    a[4]=__hmax2(a[4],u2h(v.x)); a[5]=__hmax2(a[5],u2h(v.y));
    a[6]=__hmax2(a[6],u2h(v.z)); a[7]=__hmax2(a[7],u2h(v.w));
    v = p[2];
    a[8]=__hmax2(a[8],u2h(v.x)); a[9]=__hmax2(a[9],u2h(v.y));
    a[10]=__hmax2(a[10],u2h(v.z)); a[11]=__hmax2(a[11],u2h(v.w));
    v = p[3];
    a[12]=__hmax2(a[12],u2h(v.x)); a[13]=__hmax2(a[13],u2h(v.y));
    a[14]=__hmax2(a[14],u2h(v.z)); a[15]=__hmax2(a[15],u2h(v.w));
    a[16]=__hmax2(a[16], base[16]);
}
__device__ __forceinline__ void addrow13(__half2 c[13], const __half2* base) {
    const uint4* p = reinterpret_cast<const uint4*>(base);
    uint4 v;
    v = p[0];
    c[0]=__hadd2(c[0],u2h(v.x)); c[1]=__hadd2(c[1],u2h(v.y));
    c[2]=__hadd2(c[2],u2h(v.z)); c[3]=__hadd2(c[3],u2h(v.w));
    v = p[1];
    c[4]=__hadd2(c[4],u2h(v.x)); c[5]=__hadd2(c[5],u2h(v.y));
    c[6]=__hadd2(c[6],u2h(v.z)); c[7]=__hadd2(c[7],u2h(v.w));
    v = p[2];
    c[8]=__hadd2(c[8],u2h(v.x)); c[9]=__hadd2(c[9],u2h(v.y));
    c[10]=__hadd2(c[10],u2h(v.z)); c[11]=__hadd2(c[11],u2h(v.w));
    c[12]=__hadd2(c[12], base[12]);
}
__device__ __forceinline__ void fmarow13(__half2 c[13], const __half2* base, __half2 m) {
    const uint4* p = reinterpret_cast<const uint4*>(base);
    uint4 v;
    v = p[0];
    c[0]=__hfma2(m,u2h(v.x),c[0]); c[1]=__hfma2(m,u2h(v.y),c[1]);
    c[2]=__hfma2(m,u2h(v.z),c[2]); c[3]=__hfma2(m,u2h(v.w),c[3]);
    v = p[1];
    c[4]=__hfma2(m,u2h(v.x),c[4]); c[5]=__hfma2(m,u2h(v.y),c[5]);
    c[6]=__hfma2(m,u2h(v.z),c[6]); c[7]=__hfma2(m,u2h(v.w),c[7]);
    v = p[2];
    c[8]=__hfma2(m,u2h(v.x),c[8]); c[9]=__hfma2(m,u2h(v.y),c[9]);
    c[10]=__hfma2(m,u2h(v.z),c[10]); c[11]=__hfma2(m,u2h(v.w),c[11]);
    c[12]=__hfma2(m, base[12], c[12]);
}

// blockDim=(32,19). lx = padded-x lane (valid 0..18), ly = padded-y.
// z passes: registers. x passes: shuffles. y passes: vectorized smem rows.
__device__ __forceinline__ void smooth_core_h2(__half2 col[19], __half2* xch,
                                               __half2* outb, int lx, int ly) {
    const __half2 T2 = __float2half2_rn(2.0f);
    const __half2 T3 = __float2half2_rn(3.0f);
    const __half2 INV = __float2half2_rn(1.0f/729.0f);

    // max over z (registers)
    __half2 a[17];
    #pragma unroll
    for (int z = 0; z < 17; z++) a[z] = hmax3(col[z], col[z+1], col[z+2]);

    // max over x (shuffles)
    #pragma unroll
    for (int z = 0; z < 17; z++) {
        __half2 n1 = h2shfl_down(a[z], 1);
        __half2 n2 = h2shfl_down(a[z], 2);
        a[z] = hmax3(a[z], n1, n2);
    }

    // max over y: vectorized rows [(ly*17+lx)*XROW]
    if (lx < 17) {
        uint4* row = reinterpret_cast<uint4*>(xch + (ly*17 + lx)*XROW);
        row[0] = pk4(a[0], a[1], a[2], a[3]);
        row[1] = pk4(a[4], a[5], a[6], a[7]);
        row[2] = pk4(a[8], a[9], a[10], a[11]);
        row[3] = pk4(a[12], a[13], a[14], a[15]);
        reinterpret_cast<unsigned*>(row)[16] = h2u(a[16]);
    }
    __syncthreads();
    if (lx < 17 && ly < 17) {
        maxrow17(a, xch + ((ly+1)*17 + lx)*XROW);
        maxrow17(a, xch + ((ly+2)*17 + lx)*XROW);
    }

    // 5-tap over z (registers)
    __half2 c[13];
    #pragma unroll
    for (int z = 0; z < 13; z++) {
        __half2 t = __hadd2(a[z], a[z+4]);
        t = __hfma2(T2, __hadd2(a[z+1], a[z+3]), t);
        c[z] = __hfma2(T3, a[z+2], t);
    }

    // 5-tap over x (shuffles)
    #pragma unroll
    for (int z = 0; z < 13; z++) {
        __half2 s1 = h2shfl_down(c[z], 1);
        __half2 s2 = h2shfl_down(c[z], 2);
        __half2 s3 = h2shfl_down(c[z], 3);
        __half2 s4 = h2shfl_down(c[z], 4);
        __half2 t = __hadd2(c[z], s4);
        t = __hfma2(T2, __hadd2(s1, s3), t);
        c[z] = __hfma2(T3, s2, t);
    }

    // 5-tap over y: vectorized rows [(ly*13+lx)*XROW]
    __syncthreads();
    if (lx < 13 && ly < 17) {
        uint4* row = reinterpret_cast<uint4*>(xch + (ly*13 + lx)*XROW);
        row[0] = pk4(c[0], c[1], c[2], c[3]);
        row[1] = pk4(c[4], c[5], c[6], c[7]);
        row[2] = pk4(c[8], c[9], c[10], c[11]);
        reinterpret_cast<unsigned*>(row)[12] = h2u(c[12]);
    }
    __syncthreads();
    if (lx < 13 && ly < 13) {
        addrow13(c, xch + ((ly+4)*13 + lx)*XROW);
        fmarow13(c, xch + ((ly+1)*13 + lx)*XROW, T2);
        fmarow13(c, xch + ((ly+3)*13 + lx)*XROW, T2);
        fmarow13(c, xch + ((ly+2)*13 + lx)*XROW, T3);
        #pragma unroll
        for (int z = 0; z < 13; z++)
            outb[z*169 + ly*13 + lx] = __hmul2(c[z], INV);
    }
}

__device__ __forceinline__ void store_pair(const __half2* outb, __half* d0, __half* d1,
                                           int tid) {
    const __half2 Z = __float2half2_rn(0.0f);
    for (int i = tid; i < VPAD/2; i += NT) {
        int i0 = 2*i;
        __half2 v0 = (i0     < NVOX) ? outb[i0]     : Z;
        __half2 v1 = (i0 + 1 < NVOX) ? outb[i0 + 1] : Z;
        *reinterpret_cast<__half2*>(d0 + i0) = __lows2half2(v0, v1);
        *reinterpret_cast<__half2*>(d1 + i0) = __highs2half2(v0, v1);
    }
}

// ---------------- Kernel A: S1 = smooth(a1 + a0*cost), paired ----------------
__global__ void __launch_bounds__(NT, 3) k_smooth1(
    const float* __restrict__ cost, const float* __restrict__ alpha) {
    __shared__ __align__(16) __half2 xch[XCH_H2];
    __shared__ __half2 outb[NVOX];
    __shared__ __half2 inb[NVOX];
    int p = blockIdx.x;
    int lx = threadIdx.x, ly = threadIdx.y;
    int tid = ly*32 + lx;
    float a0 = alpha[0], a1 = alpha[1];
    const float* s0 = cost + (size_t)(2*p) * NVOX;
    const float* s1 = cost + (size_t)(2*p + 1) * NVOX;

    for (int i = tid; i < NVOX; i += NT)
        inb[i] = __floats2half2_rn(a1 + a0 * __ldg(s0 + i), a1 + a0 * __ldg(s1 + i));
    __syncthreads();

    int cx = min(max(lx - 3, 0), 12);
    int cy = min(max(ly - 3, 0), 12);
    __half2 col[19];
    #pragma unroll
    for (int z = 0; z < 19; z++) {
        int cz = min(max(z - 3, 0), 12);
        col[z] = inb[cz*169 + cy*13 + cx];
    }
    smooth_core_h2(col, xch, outb, lx, ly);
    __syncthreads();
    store_pair(outb, g_S1 + (size_t)(2*p)*VPAD, g_S1 + (size_t)(2*p+1)*VPAD, tid);
}

// ------- Kernel B: c2 = blend(cost, gatherW(S1)); S2 = smooth(c2), paired -------
__global__ void __launch_bounds__(NT, 3) k_gather_smooth(
    const float* __restrict__ cost, const int* __restrict__ knn,
    const float* __restrict__ dist, const float* __restrict__ alpha) {
    __shared__ __align__(16) __half2 xch[XCH_H2];
    __shared__ __half2 outb[NVOX];
    __shared__ __half2 c2[VPAD];          // interleaved: half element 2*v+h
    __shared__ float wsh[2][KNN];
    __shared__ int   nbsh[2][KNN];
    __shared__ float sninv[2];
    int p = blockIdx.x;
    int lx = threadIdx.x, ly = threadIdx.y;
    int tid = ly*32 + lx;

    if (tid < 16) {
        int h = tid >> 3, k = tid & 7;
        int n = 2*p + h;
        wsh[h][k] = __expf(-__ldg(&dist[n*KNN + k]) * (1.0f/200.0f)); // 2*SIGMA^2=200
        nbsh[h][k] = __ldg(&knn[n*KNN + k]);
    }
    __syncthreads();
    if (tid < 2) {
        float s = 0.0f;
        #pragma unroll
        for (int k = 0; k < KNN; k++) s += wsh[tid][k];
        sninv[tid] = 1.0f / s;
    }
    __syncthreads();

    float a0 = alpha[0], a1 = alpha[1], a2 = alpha[2], a3 = alpha[3], a4 = alpha[4];

    // 552 threads: one (volume h, chunk) each, 8 LDG.128 per thread
    if (tid < 2*NCHUNK) {
        int h = tid / NCHUNK;
        int cch = tid - h*NCHUNK;
        int vbase = cch * 8;
        float acc[8];
        #pragma unroll
        for (int j = 0; j < 8; j++) acc[j] = 0.0f;
        #pragma unroll
        for (int k = 0; k < KNN; k++) {
            float w = wsh[h][k];
            const uint4* np = reinterpret_cast<const uint4*>(
                g_S1 + (size_t)nbsh[h][k] * VPAD);
            uint4 raw = __ldg(&np[cch]);
            float2 f0 = __half22float2(u2h(raw.x));
            float2 f1 = __half22float2(u2h(raw.y));
            float2 f2 = __half22float2(u2h(raw.z));
            float2 f3 = __half22float2(u2h(raw.w));
            acc[0] += w*f0.x; acc[1] += w*f0.y;
            acc[2] += w*f1.x; acc[3] += w*f1.y;
            acc[4] += w*f2.x; acc[5] += w*f2.y;
            acc[6] += w*f3.x; acc[7] += w*f3.y;
        }
        const float* src = cost + (size_t)(2*p + h) * NVOX;
        float ninv = sninv[h];
        __half* c2h = reinterpret_cast<__half*>(c2);
        #pragma unroll
        for (int j = 0; j < 8; j++) {
            int v = vbase + j;
            float c1 = (v < NVOX) ? (a1 + a0 * __ldg(&src[v])) : 0.0f;
            c2h[2*v + h] = __float2half_rn(a4 + a2*c1 + a3*(acc[j]*ninv));
        }
    }
    __syncthreads();

    int cx = min(max(lx - 3, 0), 12);
    int cy = min(max(ly - 3, 0), 12);
    __half2 col[19];
    #pragma unroll
    for (int z = 0; z < 19; z++) {
        int cz = min(max(z - 3, 0), 12);
        col[z] = c2[cz*169 + cy*13 + cx];
    }
    smooth_core_h2(col, xch, outb, lx, ly);
    __syncthreads();
    store_pair(outb, g_S2 + (size_t)(2*p)*VPAD, g_S2 + (size_t)(2*p+1)*VPAD, tid);
}

// ------- Kernel C: out = a5 * gatherW(S2) / norm, paired + coalesced stores -------
__global__ void __launch_bounds__(CT) k_gather_out(
    const int* __restrict__ knn, const float* __restrict__ dist,
    const float* __restrict__ alpha, float* __restrict__ out) {
    __shared__ float wsh[2][KNN];
    __shared__ int   nbsh[2][KNN];
    __shared__ float sscale[2];
    __shared__ float obuf[2][VPAD];
    int p = blockIdx.x;
    int tid = threadIdx.x;

    if (tid < 16) {
        int h = tid >> 3, k = tid & 7;
        int n = 2*p + h;
        wsh[h][k] = __expf(-__ldg(&dist[n*KNN + k]) * (1.0f/200.0f));
        nbsh[h][k] = __ldg(&knn[n*KNN + k]);
    }
    __syncthreads();
    if (tid < 2) {
        float s = 0.0f;
        #pragma unroll
        for (int k = 0; k < KNN; k++) s += wsh[tid][k];
        sscale[tid] = alpha[5] / s;
    }
    __syncthreads();

    if (tid < 2*NCHUNK) {
        int h = tid / NCHUNK;
        int cch = tid - h*NCHUNK;
        float acc[8];
        #pragma unroll
        for (int j = 0; j < 8; j++) acc[j] = 0.0f;
        #pragma unroll
        for (int k = 0; k < KNN; k++) {
            float w = wsh[h][k];
            const uint4* np = reinterpret_cast<const uint4*>(
                g_S2 + (size_t)nbsh[h][k] * VPAD);
            uint4 raw = __ldg(&np[cch]);
            float2 f0 = __half22float2(u2h(raw.x));
            float2 f1 = __half22float2(u2h(raw.y));
            float2 f2 = __half22float2(u2h(raw.z));
            float2 f3 = __half22float2(u2h(raw.w));
            acc[0] += w*f0.x; acc[1] += w*f0.y;
            acc[2] += w*f1.x; acc[3] += w*f1.y;
            acc[4] += w*f2.x; acc[5] += w*f2.y;
            acc[6] += w*f3.x; acc[7] += w*f3.y;
        }
        float sc = sscale[h];
        int vbase = cch * 8;
        #pragma unroll
        for (int j = 0; j < 8; j++) obuf[h][vbase + j] = acc[j] * sc;
    }
    __syncthreads();

    float* d0 = out + (size_t)(2*p) * NVOX;
    float* d1 = out + (size_t)(2*p + 1) * NVOX;
    for (int i = tid; i < NVOX; i += CT) {
        d0[i] = obuf[0][i];
        d1[i] = obuf[1][i];
    }
}

extern "C" void kernel_launch(void* const* d_in, const int* in_sizes, int n_in,
                              void* d_out, int out_size) {
    const float* cost  = (const float*)d_in[0];
    const int*   knn   = (const int*)d_in[1];
    const float* dist  = (const float*)d_in[2];
    const float* alpha = (const float*)d_in[3];
    float* out = (float*)d_out;
    int N = in_sizes[0] / NVOX;   // 10000
    int NP = N / 2;               // 5000 volume pairs

    dim3 blk(32, 19);
    k_smooth1<<<NP, blk>>>(cost, alpha);
    k_gather_smooth<<<NP, blk>>>(cost, knn, dist, alpha);
    k_gather_out<<<NP, CT>>>(knn, dist, alpha, out);
}

// round 12
// speedup vs baseline: 2.9019x; 1.1109x over previous
#include <cuda_runtime.h>
#include <cuda_fp16.h>

// deeds_graph: N=10000 volumes of 13^3, K=8 neighbors. Volume-paired half2 pipeline.
// S1 = smooth(a1 + a0*cost); c2 = a4 + a2*(a1+a0*cost) + a3*gatherW(S1)/norm;
// S2 = smooth(c2); out = a5*gatherW(S2)/norm.
// smooth = edge-pad(3) -> max3^3 -> (5-tap [1,2,3,2,1]/9)^3 (separable).
//
// NEW core: no shuffles. Flat 384-thread block; thread t<361 owns padded row
// (x,y) = (t%19, t/19), holding the z-extent in registers. Cross-thread passes
// are 4 smem "rounds" (write own row, sync, fused-read neighbor rows, sync)
// on z-contiguous rows of stride 20 half2 (80B) -> LDS.128/STS.128, conflict-free.
// z passes stay in registers. Out-of-extent threads compute finite garbage that
// is never consumed (guards: R1 x<17, R2 y<17, R3 x<13, R4 x<13&&y<13).

#define NVOX 2197          // 13^3
#define VPAD 2208          // padded halves per volume (16B chunks)
#define NCHUNK 276         // VPAD/8
#define NMAX 10000
#define KNN  8
#define NROW 361           // 19*19 padded rows
#define XROW 20            // half2 words per row (80B, 16B-aligned)
#define NTH 384            // flat block
#define CT 576             // kernel C block

__device__ __half g_S1[(size_t)NMAX * VPAD];
__device__ __half g_S2[(size_t)NMAX * VPAD];

__device__ __forceinline__ unsigned h2u(__half2 v) { return *reinterpret_cast<unsigned*>(&v); }
__device__ __forceinline__ __half2 u2h(unsigned u) { return *reinterpret_cast<__half2*>(&u); }
__device__ __forceinline__ uint4 pk4(__half2 a, __half2 b, __half2 c, __half2 d) {
    return make_uint4(h2u(a), h2u(b), h2u(c), h2u(d));
}
__device__ __forceinline__ __half2 hmax3(__half2 a, __half2 b, __half2 c) {
    return __hmax2(__hmax2(a, b), c);
}

__device__ __forceinline__ void write17(__half2* rp, const __half2 a[17]) {
    uint4* p = reinterpret_cast<uint4*>(rp);
    p[0] = pk4(a[0], a[1], a[2], a[3]);
    p[1] = pk4(a[4], a[5], a[6], a[7]);
    p[2] = pk4(a[8], a[9], a[10], a[11]);
    p[3] = pk4(a[12], a[13], a[14], a[15]);
    reinterpret_cast<unsigned*>(rp)[16] = h2u(a[16]);
}
__device__ __forceinline__ void write13(__half2* rp, const __half2 c[13]) {
    uint4* p = reinterpret_cast<uint4*>(rp);
    p[0] = pk4(c[0], c[1], c[2], c[3]);
    p[1] = pk4(c[4], c[5], c[6], c[7]);
    p[2] = pk4(c[8], c[9], c[10], c[11]);
    reinterpret_cast<unsigned*>(rp)[12] = h2u(c[12]);
}

__device__ __forceinline__ void maxrow17(__half2 a[17], const __half2* base) {
    const uint4* p = reinterpret_cast<const uint4*>(base);
    uint4 v;
    v = p[0];
    a[0]=__hmax2(a[0],u2h(v.x)); a[1]=__hmax2(a[1],u2h(v.y));
    a[2]=__hmax2(a[2],u2h(v.z)); a[3]=__hmax2(a[3],u2h(v.w));
    v = p[1];
    a[4]=__hmax2(a[4],u2h(v.x)); a[5]=__hmax2(a[5],u2h(v.y));
    a[6]=__hmax2(a[6],u2h(v.z)); a[7]=__hmax2(a[7],u2h(v.w));
    v = p[2];
    a[8]=__hmax2(a[8],u2h(v.x)); a[9]=__hmax2(a[9],u2h(v.y));
    a[10]=__hmax2(a[10],u2h(v.z)); a[11]=__hmax2(a[11],u2h(v.w));
    v = p[3];
    a[12]=__hmax2(a[12],u2h(v.x)); a[13]=__hmax2(a[13],u2h(v.y));
    a[14]=__hmax2(a[14],u2h(v.z)); a[15]=__hmax2(a[15],u2h(v.w));
    a[16]=__hmax2(a[16], base[16]);
}
__device__ __forceinline__ void addrow13(__half2 c[13], const __half2* base) {
    const uint4* p = reinterpret_cast<const uint4*>(base);
    uint4 v;
    v = p[0];
    c[0]=__hadd2(c[0],u2h(v.x)); c[1]=__hadd2(c[1],u2h(v.y));
    c[2]=__hadd2(c[2],u2h(v.z)); c[3]=__hadd2(c[3],u2h(v.w));
    v = p[1];
    c[4]=__hadd2(c[4],u2h(v.x)); c[5]=__hadd2(c[5],u2h(v.y));
    c[6]=__hadd2(c[6],u2h(v.z)); c[7]=__hadd2(c[7],u2h(v.w));
    v = p[2];
    c[8]=__hadd2(c[8],u2h(v.x)); c[9]=__hadd2(c[9],u2h(v.y));
    c[10]=__hadd2(c[10],u2h(v.z)); c[11]=__hadd2(c[11],u2h(v.w));
    c[12]=__hadd2(c[12], base[12]);
}
__device__ __forceinline__ void fmarow13(__half2 c[13], const __half2* base, __half2 m) {
    const uint4* p = reinterpret_cast<const uint4*>(base);
    uint4 v;
    v = p[0];
    c[0]=__hfma2(m,u2h(v.x),c[0]); c[1]=__hfma2(m,u2h(v.y),c[1]);
    c[2]=__hfma2(m,u2h(v.z),c[2]); c[3]=__hfma2(m,u2h(v.w),c[3]);
    v = p[1];
    c[4]=__hfma2(m,u2h(v.x),c[4]); c[5]=__hfma2(m,u2h(v.y),c[5]);
    c[6]=__hfma2(m,u2h(v.z),c[6]); c[7]=__hfma2(m,u2h(v.w),c[7]);
    v = p[2];
    c[8]=__hfma2(m,u2h(v.x),c[8]); c[9]=__hfma2(m,u2h(v.y),c[9]);
    c[10]=__hfma2(m,u2h(v.z),c[10]); c[11]=__hfma2(m,u2h(v.w),c[11]);
    c[12]=__hfma2(m, base[12], c[12]);
}

// col: 19 padded-z half2 values of row (x,y)=(t%19,t/19). Result -> outb[(x*13+y)*13+z].
__device__ __forceinline__ void smooth_rounds(__half2 col[19], __half2* xch,
                                              __half2* outb, int t) {
    const __half2 T2 = __float2half2_rn(2.0f);
    const __half2 T3 = __float2half2_rn(3.0f);
    const __half2 INV = __float2half2_rn(1.0f/729.0f);
    int x = t % 19, y = t / 19;
    bool own = t < NROW;
    __half2* myrow = xch + t * XROW;

    // max over z (registers): 19 -> 17
    __half2 a[17];
    #pragma unroll
    for (int z = 0; z < 17; z++) a[z] = hmax3(col[z], col[z+1], col[z+2]);

    // R1: max over x
    if (own) write17(myrow, a);
    __syncthreads();
    if (own && x < 17) {
        maxrow17(a, xch + (t+1)*XROW);
        maxrow17(a, xch + (t+2)*XROW);
    }
    __syncthreads();

    // R2: max over y
    if (own) write17(myrow, a);
    __syncthreads();
    if (own && y < 17) {
        maxrow17(a, xch + (t+19)*XROW);
        maxrow17(a, xch + (t+38)*XROW);
    }
    __syncthreads();

    // 5-tap over z (registers): 17 -> 13
    __half2 c[13];
    #pragma unroll
    for (int z = 0; z < 13; z++) {
        __half2 s = __hadd2(a[z], a[z+4]);
        s = __hfma2(T2, __hadd2(a[z+1], a[z+3]), s);
        c[z] = __hfma2(T3, a[z+2], s);
    }

    // R3: 5-tap over x
    if (own) write13(myrow, c);
    __syncthreads();
    if (own && x < 13) {
        fmarow13(c, xch + (t+1)*XROW, T2);
        fmarow13(c, xch + (t+2)*XROW, T3);
        fmarow13(c, xch + (t+3)*XROW, T2);
        addrow13(c, xch + (t+4)*XROW);
    }
    __syncthreads();

    // R4: 5-tap over y + final write
    if (own) write13(myrow, c);
    __syncthreads();
    if (own && x < 13 && y < 13) {
        fmarow13(c, xch + (t+19)*XROW, T2);
        fmarow13(c, xch + (t+38)*XROW, T3);
        fmarow13(c, xch + (t+57)*XROW, T2);
        addrow13(c, xch + (t+76)*XROW);
        int base = (x*13 + y)*13;
        #pragma unroll
        for (int z = 0; z < 13; z++) outb[base + z] = __hmul2(c[z], INV);
    }
}

// build padded col from linear pair buffer (v = (x*13+y)*13+z)
__device__ __forceinline__ void build_col(const __half2* lin, __half2 col[19], int t) {
    if (t < NROW) {
        int x = t % 19, y = t / 19;
        int cx = min(max(x - 3, 0), 12);
        int cy = min(max(y - 3, 0), 12);
        const __half2* src = lin + (cx*13 + cy)*13;
        __half2 vv[13];
        #pragma unroll
        for (int z = 0; z < 13; z++) vv[z] = src[z];
        #pragma unroll
        for (int pz = 0; pz < 19; pz++) col[pz] = vv[min(max(pz - 3, 0), 12)];
    }
}

__device__ __forceinline__ void store_pair(const __half2* outb, __half* d0, __half* d1,
                                           int t) {
    const __half2 Z = __float2half2_rn(0.0f);
    for (int i = t; i < VPAD/2; i += NTH) {
        int i0 = 2*i;
        __half2 v0 = (i0     < NVOX) ? outb[i0]     : Z;
        __half2 v1 = (i0 + 1 < NVOX) ? outb[i0 + 1] : Z;
        *reinterpret_cast<__half2*>(d0 + i0) = __lows2half2(v0, v1);
        *reinterpret_cast<__half2*>(d1 + i0) = __highs2half2(v0, v1);
    }
}

// ---------------- Kernel A: S1 = smooth(a1 + a0*cost), paired ----------------
__global__ void __launch_bounds__(NTH, 4) k_smooth1(
    const float* __restrict__ cost, const float* __restrict__ alpha) {
    __shared__ __align__(16) __half2 xch[NROW * XROW];
    __shared__ __align__(16) __half2 lin[VPAD];
    int p = blockIdx.x, t = threadIdx.x;
    float a0 = alpha[0], a1 = alpha[1];
    const float* s0 = cost + (size_t)(2*p) * NVOX;
    const float* s1 = cost + (size_t)(2*p + 1) * NVOX;

    for (int v = t; v < NVOX; v += NTH)
        lin[v] = __floats2half2_rn(a1 + a0 * __ldg(s0 + v), a1 + a0 * __ldg(s1 + v));
    __syncthreads();

    __half2 col[19];
    build_col(lin, col, t);
    smooth_rounds(col, xch, lin, t);   // outb reuses lin (reads done pre-R1)
    __syncthreads();
    store_pair(lin, g_S1 + (size_t)(2*p)*VPAD, g_S1 + (size_t)(2*p+1)*VPAD, t);
}

// ------- Kernel B: c2 = blend(cost, gatherW(S1)); S2 = smooth(c2), paired -------
__global__ void __launch_bounds__(NTH, 4) k_gather_smooth(
    const float* __restrict__ cost, const int* __restrict__ knn,
    const float* __restrict__ dist, const float* __restrict__ alpha) {
    __shared__ __align__(16) __half2 xch[NROW * XROW];
    __shared__ __align__(16) __half2 lin[VPAD];
    __shared__ float wsh[2][KNN];
    __shared__ int   nbsh[2][KNN];
    __shared__ float sninv[2];
    int p = blockIdx.x, t = threadIdx.x;

    if (t < 16) {
        int h = t >> 3, k = t & 7;
        int n = 2*p + h;
        wsh[h][k] = __expf(-__ldg(&dist[n*KNN + k]) * (1.0f/200.0f)); // 2*SIGMA^2=200
        nbsh[h][k] = __ldg(&knn[n*KNN + k]);
    }
    __syncthreads();
    if (t < 2) {
        float s = 0.0f;
        #pragma unroll
        for (int k = 0; k < KNN; k++) s += wsh[t][k];
        sninv[t] = 1.0f / s;
    }
    __syncthreads();

    float a0 = alpha[0], a1 = alpha[1], a2 = alpha[2], a3 = alpha[3], a4 = alpha[4];

    // 276 threads: one chunk (8 voxels) x both volumes; 16 LDG.128 each (MLP)
    if (t < NCHUNK) {
        int cch = t, vbase = cch * 8;
        float res[2][8];
        #pragma unroll
        for (int h = 0; h < 2; h++) {
            float acc[8];
            #pragma unroll
            for (int j = 0; j < 8; j++) acc[j] = 0.0f;
            #pragma unroll
            for (int k = 0; k < KNN; k++) {
                float w = wsh[h][k];
                const uint4* np = reinterpret_cast<const uint4*>(
                    g_S1 + (size_t)nbsh[h][k] * VPAD);
                uint4 raw = __ldg(&np[cch]);
                float2 f0 = __half22float2(u2h(raw.x));
                float2 f1 = __half22float2(u2h(raw.y));
                float2 f2 = __half22float2(u2h(raw.z));
                float2 f3 = __half22float2(u2h(raw.w));
                acc[0] += w*f0.x; acc[1] += w*f0.y;
                acc[2] += w*f1.x; acc[3] += w*f1.y;
                acc[4] += w*f2.x; acc[5] += w*f2.y;
                acc[6] += w*f3.x; acc[7] += w*f3.y;
            }
            const float* src = cost + (size_t)(2*p + h) * NVOX;
            float ninv = sninv[h];
            #pragma unroll
            for (int j = 0; j < 8; j++) {
                int v = vbase + j;
                float c1 = (v < NVOX) ? (a1 + a0 * __ldg(&src[v])) : 0.0f;
                res[h][j] = a4 + a2*c1 + a3*(acc[j]*ninv);
            }
        }
        // pack 8 half2 (lo=vol0, hi=vol1) -> 2 x STS.128
        uint4 w0, w1;
        w0.x = h2u(__floats2half2_rn(res[0][0], res[1][0]));
        w0.y = h2u(__floats2half2_rn(res[0][1], res[1][1]));
        w0.z = h2u(__floats2half2_rn(res[0][2], res[1][2]));
        w0.w = h2u(__floats2half2_rn(res[0][3], res[1][3]));
        w1.x = h2u(__floats2half2_rn(res[0][4], res[1][4]));
        w1.y = h2u(__floats2half2_rn(res[0][5], res[1][5]));
        w1.z = h2u(__floats2half2_rn(res[0][6], res[1][6]));
        w1.w = h2u(__floats2half2_rn(res[0][7], res[1][7]));
        uint4* lp = reinterpret_cast<uint4*>(lin);
        lp[cch*2]     = w0;
        lp[cch*2 + 1] = w1;
    }
    __syncthreads();

    __half2 col[19];
    build_col(lin, col, t);
    smooth_rounds(col, xch, lin, t);
    __syncthreads();
    store_pair(lin, g_S2 + (size_t)(2*p)*VPAD, g_S2 + (size_t)(2*p+1)*VPAD, t);
}

// ------- Kernel C: out = a5 * gatherW(S2) / norm, paired + coalesced stores -------
__global__ void __launch_bounds__(CT) k_gather_out(
    const int* __restrict__ knn, const float* __restrict__ dist,
    const float* __restrict__ alpha, float* __restrict__ out) {
    __shared__ float wsh[2][KNN];
    __shared__ int   nbsh[2][KNN];
    __shared__ float sscale[2];
    __shared__ float obuf[2][VPAD];
    int p = blockIdx.x;
    int tid = threadIdx.x;

    if (tid < 16) {
        int h = tid >> 3, k = tid & 7;
        int n = 2*p + h;
        wsh[h][k] = __expf(-__ldg(&dist[n*KNN + k]) * (1.0f/200.0f));
        nbsh[h][k] = __ldg(&knn[n*KNN + k]);
    }
    __syncthreads();
    if (tid < 2) {
        float s = 0.0f;
        #pragma unroll
        for (int k = 0; k < KNN; k++) s += wsh[tid][k];
        sscale[tid] = alpha[5] / s;
    }
    __syncthreads();

    if (tid < 2*NCHUNK) {
        int h = tid / NCHUNK;
        int cch = tid - h*NCHUNK;
        float acc[8];
        #pragma unroll
        for (int j = 0; j < 8; j++) acc[j] = 0.0f;
        #pragma unroll
        for (int k = 0; k < KNN; k++) {
            float w = wsh[h][k];
            const uint4* np = reinterpret_cast<const uint4*>(
                g_S2 + (size_t)nbsh[h][k] * VPAD);
            uint4 raw = __ldg(&np[cch]);
            float2 f0 = __half22float2(u2h(raw.x));
            float2 f1 = __half22float2(u2h(raw.y));
            float2 f2 = __half22float2(u2h(raw.z));
            float2 f3 = __half22float2(u2h(raw.w));
            acc[0] += w*f0.x; acc[1] += w*f0.y;
            acc[2] += w*f1.x; acc[3] += w*f1.y;
            acc[4] += w*f2.x; acc[5] += w*f2.y;
            acc[6] += w*f3.x; acc[7] += w*f3.y;
        }
        float sc = sscale[h];
        int vbase = cch * 8;
        #pragma unroll
        for (int j = 0; j < 8; j++) obuf[h][vbase + j] = acc[j] * sc;
    }
    __syncthreads();

    float* d0 = out + (size_t)(2*p) * NVOX;
    float* d1 = out + (size_t)(2*p + 1) * NVOX;
    for (int i = tid; i < NVOX; i += CT) {
        d0[i] = obuf[0][i];
        d1[i] = obuf[1][i];
    }
}

extern "C" void kernel_launch(void* const* d_in, const int* in_sizes, int n_in,
                              void* d_out, int out_size) {
    const float* cost  = (const float*)d_in[0];
    const int*   knn   = (const int*)d_in[1];
    const float* dist  = (const float*)d_in[2];
    const float* alpha = (const float*)d_in[3];
    float* out = (float*)d_out;
    int N = in_sizes[0] / NVOX;   // 10000
    int NP = N / 2;               // 5000 volume pairs

    k_smooth1<<<NP, NTH>>>(cost, alpha);
    k_gather_smooth<<<NP, NTH>>>(cost, knn, dist, alpha);
    k_gather_out<<<NP, CT>>>(knn, dist, alpha, out);
}